// round 1
// baseline (speedup 1.0000x reference)
#include <cuda_runtime.h>

// Problem constants
namespace {
constexpr int kB   = 2;
constexpr int kS   = 2048;
constexpr int kDin = 2048;
constexpr int kNH  = 32;
constexpr int kNKV = 8;
constexpr int kHD  = 64;
constexpr int kDout = 2048;           // kNH * kHD
constexpr int kM   = kB * kS;         // 4096 rows
constexpr int kKV  = kNKV * kHD;      // 512
}

// Scratch (static device allocations are allowed; cudaMalloc is not)
__device__ float g_Q[kM * kDout];     // 32 MB
__device__ float g_Kp[kM * kKV];      // 8 MB
__device__ float g_Vp[kM * kKV];      // 8 MB
__device__ float g_Ctx[kM * kDout];   // 32 MB

// ---------------------------------------------------------------------------
// C[M,N] = A[M,K] @ B[N,K]^T   (both operands row-major with contiguous K)
// 128x128 block tile, BK=8, 256 threads, 8x8 register tile per thread.
// All dims here are multiples of the tile sizes (M=4096, N in {2048,512}, K=2048).
// ---------------------------------------------------------------------------
__global__ __launch_bounds__(256) void sgemm_nt(
    const float* __restrict__ A, const float* __restrict__ Bw,
    float* __restrict__ C, int M, int N, int K) {
  constexpr int BM = 128, BN = 128, BK = 8;
  __shared__ float As[BK][BM + 4];
  __shared__ float Bs[BK][BN + 4];
  const int m0 = blockIdx.y * BM, n0 = blockIdx.x * BN;
  const int t  = threadIdx.x;
  const int tx = t & 15, ty = t >> 4;
  const int lrow = t >> 1, lc4 = (t & 1) * 4;
  const float* Ap = A  + (m0 + lrow) * K + lc4;
  const float* Bp = Bw + (n0 + lrow) * K + lc4;
  float acc[8][8] = {};
  for (int k0 = 0; k0 < K; k0 += BK) {
    float4 av = *(const float4*)(Ap + k0);
    float4 bv = *(const float4*)(Bp + k0);
    As[lc4+0][lrow] = av.x; As[lc4+1][lrow] = av.y;
    As[lc4+2][lrow] = av.z; As[lc4+3][lrow] = av.w;
    Bs[lc4+0][lrow] = bv.x; Bs[lc4+1][lrow] = bv.y;
    Bs[lc4+2][lrow] = bv.z; Bs[lc4+3][lrow] = bv.w;
    __syncthreads();
#pragma unroll
    for (int kk = 0; kk < BK; kk++) {
      float a[8], b[8];
      *(float4*)&a[0] = *(const float4*)&As[kk][ty * 8];
      *(float4*)&a[4] = *(const float4*)&As[kk][ty * 8 + 4];
      *(float4*)&b[0] = *(const float4*)&Bs[kk][tx * 8];
      *(float4*)&b[4] = *(const float4*)&Bs[kk][tx * 8 + 4];
#pragma unroll
      for (int i = 0; i < 8; i++)
#pragma unroll
        for (int j = 0; j < 8; j++) acc[i][j] = fmaf(a[i], b[j], acc[i][j]);
    }
    __syncthreads();
  }
#pragma unroll
  for (int i = 0; i < 8; i++) {
    float* Cp = C + (m0 + ty * 8 + i) * N + n0 + tx * 8;
    *(float4*)Cp       = make_float4(acc[i][0], acc[i][1], acc[i][2], acc[i][3]);
    *(float4*)(Cp + 4) = make_float4(acc[i][4], acc[i][5], acc[i][6], acc[i][7]);
  }
}

// ---------------------------------------------------------------------------
// Repack K/V projections [b*S, g*64+d] -> keys/values [b, g, s, d]
// (these ARE the second/third outputs; attention also reads this layout,
//  giving it fully contiguous per-(b,g) tiles)
// ---------------------------------------------------------------------------
__global__ __launch_bounds__(256) void transpose_kv(
    const float* __restrict__ Kb, const float* __restrict__ Vb,
    float* __restrict__ keys, float* __restrict__ values) {
  int idx = blockIdx.x * blockDim.x + threadIdx.x;     // float4 granularity
  constexpr int total4 = kB * kNKV * kS * kHD / 4;     // 524288
  if (idx >= total4) return;
  int e = idx * 4;
  int d = e & 63;
  int s = (e >> 6) & (kS - 1);
  int g = (e >> 17) & (kNKV - 1);
  int b = e >> 20;
  int src = (b * kS + s) * kKV + g * kHD + d;
  ((float4*)keys)[idx]   = *(const float4*)(Kb + src);
  ((float4*)values)[idx] = *(const float4*)(Vb + src);
}

// ---------------------------------------------------------------------------
// Flash attention, fp32. One block = 64 queries of one (b, head).
// 256 threads (16x16), 4x4 register tiles for both QK^T and PV.
// Q/K stored d-major (transposed) in smem for conflict-free GEMM reads.
// ---------------------------------------------------------------------------
__global__ __launch_bounds__(256) void attn_kernel(
    const float* __restrict__ Q, const float* __restrict__ Kc,
    const float* __restrict__ Vc, float* __restrict__ Ctx) {
  extern __shared__ float sm[];
  float* Qst = sm;             // [64 d][68]  (d-major, q contiguous)
  float* Kst = Qst + 64 * 68;  // [64 d][68]  (d-major, k contiguous)
  float* Vs  = Kst + 64 * 68;  // [64 k][68]  (k-major, d contiguous)
  float* Ps  = Vs  + 64 * 68;  // [64 q][68]  (q-major, k contiguous)

  const int qt = blockIdx.x;           // 0..31
  const int hb = blockIdx.y;           // 0..63
  const int b = hb >> 5, h = hb & 31, g = h >> 2;
  const int t = threadIdx.x, tx = t & 15, ty = t >> 4;
  const int q0 = qt * 64;

  const float* Qbase = Q  + (b * kS + q0) * kDout + h * kHD;
  const float* Kbase = Kc + (b * kNKV + g) * kS * kHD;
  const float* Vbase = Vc + (b * kNKV + g) * kS * kHD;

  // Load Q tile transposed into smem
  {
    const int d4 = tx * 4;
#pragma unroll
    for (int r = 0; r < 4; r++) {
      int qq = ty + r * 16;
      float4 v = *(const float4*)(Qbase + qq * kDout + d4);
      Qst[(d4 + 0) * 68 + qq] = v.x;
      Qst[(d4 + 1) * 68 + qq] = v.y;
      Qst[(d4 + 2) * 68 + qq] = v.z;
      Qst[(d4 + 3) * 68 + qq] = v.w;
    }
  }

  float acc[4][4] = {};
  float Mr[4] = {-1e30f, -1e30f, -1e30f, -1e30f};
  float Lr[4] = {};

  for (int kt = 0; kt <= qt; kt++) {
    const int k0 = kt * 64;
    const int d4 = tx * 4;
#pragma unroll
    for (int r = 0; r < 4; r++) {
      int kk = ty + r * 16;
      float4 kv = *(const float4*)(Kbase + (k0 + kk) * kHD + d4);
      Kst[(d4 + 0) * 68 + kk] = kv.x;
      Kst[(d4 + 1) * 68 + kk] = kv.y;
      Kst[(d4 + 2) * 68 + kk] = kv.z;
      Kst[(d4 + 3) * 68 + kk] = kv.w;
      float4 vv = *(const float4*)(Vbase + (k0 + kk) * kHD + d4);
      *(float4*)&Vs[kk * 68 + d4] = vv;
    }
    __syncthreads();

    // S = Q K^T (contract over d)
    float sreg[4][4] = {};
#pragma unroll 8
    for (int d = 0; d < 64; d++) {
      float4 qv = *(const float4*)&Qst[d * 68 + ty * 4];
      float4 kv = *(const float4*)&Kst[d * 68 + tx * 4];
      float qa[4] = {qv.x, qv.y, qv.z, qv.w};
      float ka[4] = {kv.x, kv.y, kv.z, kv.w};
#pragma unroll
      for (int i = 0; i < 4; i++)
#pragma unroll
        for (int j = 0; j < 4; j++) sreg[i][j] = fmaf(qa[i], ka[j], sreg[i][j]);
    }

    // Scale + causal mask (only bites on the diagonal tile)
#pragma unroll
    for (int i = 0; i < 4; i++)
#pragma unroll
      for (int j = 0; j < 4; j++) {
        float s = sreg[i][j] * 0.125f;
        if (k0 + tx * 4 + j > q0 + ty * 4 + i) s = -1e30f;
        sreg[i][j] = s;
      }

    // Row max across the 16 tx lanes (half-warp shuffles)
    float ml[4];
#pragma unroll
    for (int i = 0; i < 4; i++)
      ml[i] = fmaxf(fmaxf(sreg[i][0], sreg[i][1]), fmaxf(sreg[i][2], sreg[i][3]));
#pragma unroll
    for (int off = 8; off >= 1; off >>= 1)
#pragma unroll
      for (int i = 0; i < 4; i++)
        ml[i] = fmaxf(ml[i], __shfl_xor_sync(0xffffffffu, ml[i], off));

    float esc[4], pl[4];
#pragma unroll
    for (int i = 0; i < 4; i++) {
      float mn = fmaxf(Mr[i], ml[i]);
      esc[i] = __expf(Mr[i] - mn);
      Mr[i] = mn;
      float s = 0.f;
#pragma unroll
      for (int j = 0; j < 4; j++) {
        float p = __expf(sreg[i][j] - mn);
        sreg[i][j] = p;
        s += p;
      }
      pl[i] = s;
    }
#pragma unroll
    for (int off = 8; off >= 1; off >>= 1)
#pragma unroll
      for (int i = 0; i < 4; i++)
        pl[i] += __shfl_xor_sync(0xffffffffu, pl[i], off);

#pragma unroll
    for (int i = 0; i < 4; i++) {
      Lr[i] = Lr[i] * esc[i] + pl[i];
#pragma unroll
      for (int j = 0; j < 4; j++) acc[i][j] *= esc[i];
      *(float4*)&Ps[(ty * 4 + i) * 68 + tx * 4] =
          make_float4(sreg[i][0], sreg[i][1], sreg[i][2], sreg[i][3]);
    }
    __syncthreads();

    // acc += P V (contract over k)
#pragma unroll 8
    for (int kk = 0; kk < 64; kk++) {
      float4 vv = *(const float4*)&Vs[kk * 68 + tx * 4];
      float va[4] = {vv.x, vv.y, vv.z, vv.w};
      float pa[4];
#pragma unroll
      for (int i = 0; i < 4; i++) pa[i] = Ps[(ty * 4 + i) * 68 + kk];
#pragma unroll
      for (int i = 0; i < 4; i++)
#pragma unroll
        for (int j = 0; j < 4; j++) acc[i][j] = fmaf(pa[i], va[j], acc[i][j]);
    }
    __syncthreads();
  }

  float* Cb = Ctx + (b * kS + q0) * kDout + h * kHD;
#pragma unroll
  for (int i = 0; i < 4; i++) {
    float inv = 1.f / Lr[i];
    *(float4*)(Cb + (ty * 4 + i) * kDout + tx * 4) =
        make_float4(acc[i][0] * inv, acc[i][1] * inv,
                    acc[i][2] * inv, acc[i][3] * inv);
  }
}

// ---------------------------------------------------------------------------
extern "C" void kernel_launch(void* const* d_in, const int* in_sizes, int n_in,
                              void* d_out, int out_size) {
  const float* x  = (const float*)d_in[0];
  const float* Wq = (const float*)d_in[1];
  const float* Wk = (const float*)d_in[2];
  const float* Wv = (const float*)d_in[3];
  const float* Wo = (const float*)d_in[4];

  float* out    = (float*)d_out;                    // [2,2048,2048]
  float* keys   = out + kM * kDout;                 // [2,8,2048,64]
  float* values = keys + kB * kNKV * kS * kHD;      // [2,8,2048,64]

  float *qb, *kb, *vb, *cb;
  cudaGetSymbolAddress((void**)&qb, g_Q);
  cudaGetSymbolAddress((void**)&kb, g_Kp);
  cudaGetSymbolAddress((void**)&vb, g_Vp);
  cudaGetSymbolAddress((void**)&cb, g_Ctx);

  dim3 blk(256);
  // Projections
  sgemm_nt<<<dim3(kDout / 128, kM / 128), blk>>>(x, Wq, qb, kM, kDout, kDin);
  sgemm_nt<<<dim3(kKV / 128, kM / 128), blk>>>(x, Wk, kb, kM, kKV, kDin);
  sgemm_nt<<<dim3(kKV / 128, kM / 128), blk>>>(x, Wv, vb, kM, kKV, kDin);
  // Emit keys/values outputs (also the attention-side K/V layout)
  transpose_kv<<<(kB * kNKV * kS * kHD / 4 + 255) / 256, blk>>>(kb, vb, keys, values);
  // Attention
  constexpr int kSmem = 4 * 64 * 68 * (int)sizeof(float);  // 69632 B
  cudaFuncSetAttribute(attn_kernel, cudaFuncAttributeMaxDynamicSharedMemorySize, kSmem);
  attn_kernel<<<dim3(kS / 64, kB * kNH), blk, kSmem>>>(qb, keys, values, cb);
  // Output projection
  sgemm_nt<<<dim3(kDout / 128, kM / 128), blk>>>(cb, Wo, out, kM, kDout, kDin);
}

// round 3
// speedup vs baseline: 2.0376x; 2.0376x over previous
#include <cuda_runtime.h>
#include <cstdint>

// Problem constants
namespace {
constexpr int kB   = 2;
constexpr int kS   = 2048;
constexpr int kDin = 2048;
constexpr int kNH  = 32;
constexpr int kNKV = 8;
constexpr int kHD  = 64;
constexpr int kDout = 2048;           // kNH * kHD
constexpr int kM   = kB * kS;         // 4096 rows
constexpr int kKV  = kNKV * kHD;      // 512
}

// Scratch (static device arrays; cudaMalloc is forbidden)
__device__ float g_Q[kM * kDout];     // 32 MB
__device__ float g_Kp[kM * kKV];      // 8 MB
__device__ float g_Vp[kM * kKV];      // 8 MB
__device__ float g_Ctx[kM * kDout];   // 32 MB

// ---------------------------------------------------------------------------
// TF32 tensor-core GEMM: C[M,N] = A[M,K] @ B[N,K]^T (both K-contiguous).
// 128x128 block tile, BK=32, cp.async double buffer, 8 warps, 32x64 warp tile,
// mma.sync.m16n8k8.tf32. Dims are multiples of tiles (M=4096, N∈{2048,512}, K=2048).
// ---------------------------------------------------------------------------
__device__ __forceinline__ uint32_t f2tf32(float f) {
  uint32_t u;
  asm("cvt.rna.tf32.f32 %0, %1;" : "=r"(u) : "f"(f));
  return u;
}

__device__ __forceinline__ void cp_async16(uint32_t smem_addr, const void* gptr) {
  asm volatile("cp.async.cg.shared.global [%0], [%1], 16;" :: "r"(smem_addr), "l"(gptr));
}

__global__ __launch_bounds__(256) void gemm_tf32_nt(
    const float* __restrict__ A, const float* __restrict__ Bw,
    float* __restrict__ C, int M, int N, int K) {
  constexpr int BM = 128, BN = 128, BK = 32, LD = 36;  // LD pad -> conflict-free frags
  extern __shared__ float smem[];
  float* As = smem;                 // [2][BM][LD]
  float* Bs = smem + 2 * BM * LD;   // [2][BN][LD]

  const int m0 = blockIdx.y * BM, n0 = blockIdx.x * BN;
  const int t = threadIdx.x;
  const int lane = t & 31, w = t >> 5;
  const int wm0 = (w & 3) * 32;     // warp M origin within block
  const int wn0 = (w >> 2) * 64;    // warp N origin within block
  const int lq = lane & 3;          // lane % 4 (k within fragment)
  const int lr8 = lane >> 2;        // lane / 4 (row/col within fragment)

  const int grow = t >> 3;          // 0..31: global-load row group
  const int gk4  = (t & 7) * 4;     // k offset (float4)

  const float* Agp = A  + (m0 + grow) * (long)K + gk4;
  const float* Bgp = Bw + (n0 + grow) * (long)K + gk4;

  uint32_t sA = (uint32_t)__cvta_generic_to_shared(As);
  uint32_t sB = (uint32_t)__cvta_generic_to_shared(Bs);

  auto load_stage = [&](int buf, int k0) {
    uint32_t abase = sA + (uint32_t)(buf * BM * LD) * 4u;
    uint32_t bbase = sB + (uint32_t)(buf * BN * LD) * 4u;
#pragma unroll
    for (int s = 0; s < 4; s++) {
      int row = grow + s * 32;
      cp_async16(abase + (uint32_t)(row * LD + gk4) * 4u, Agp + (long)s * 32 * K + k0);
      cp_async16(bbase + (uint32_t)(row * LD + gk4) * 4u, Bgp + (long)s * 32 * K + k0);
    }
    asm volatile("cp.async.commit_group;" ::: "memory");
  };

  float c[2][8][4];
#pragma unroll
  for (int i = 0; i < 2; i++)
#pragma unroll
    for (int j = 0; j < 8; j++)
#pragma unroll
      for (int r = 0; r < 4; r++) c[i][j][r] = 0.f;

  const int NIT = K / BK;
  load_stage(0, 0);

  for (int it = 0; it < NIT; it++) {
    if (it + 1 < NIT) {
      load_stage((it + 1) & 1, (it + 1) * BK);
      asm volatile("cp.async.wait_group 1;" ::: "memory");
    } else {
      asm volatile("cp.async.wait_group 0;" ::: "memory");
    }
    __syncthreads();

    const float* Ab = As + (it & 1) * BM * LD;
    const float* Bb = Bs + (it & 1) * BN * LD;

#pragma unroll
    for (int ks = 0; ks < 4; ks++) {
      const int kb = ks * 8;
      uint32_t af[2][4], bf[8][2];
#pragma unroll
      for (int mt = 0; mt < 2; mt++) {
        const float* ap = Ab + (wm0 + mt * 16 + lr8) * LD + kb + lq;
        af[mt][0] = f2tf32(ap[0]);
        af[mt][1] = f2tf32(ap[8 * LD]);
        af[mt][2] = f2tf32(ap[4]);
        af[mt][3] = f2tf32(ap[8 * LD + 4]);
      }
#pragma unroll
      for (int nt = 0; nt < 8; nt++) {
        const float* bp = Bb + (wn0 + nt * 8 + lr8) * LD + kb + lq;
        bf[nt][0] = f2tf32(bp[0]);
        bf[nt][1] = f2tf32(bp[4]);
      }
#pragma unroll
      for (int mt = 0; mt < 2; mt++)
#pragma unroll
        for (int nt = 0; nt < 8; nt++) {
          asm volatile(
              "mma.sync.aligned.m16n8k8.row.col.f32.tf32.tf32.f32 "
              "{%0,%1,%2,%3}, {%4,%5,%6,%7}, {%8,%9}, {%0,%1,%2,%3};"
              : "+f"(c[mt][nt][0]), "+f"(c[mt][nt][1]),
                "+f"(c[mt][nt][2]), "+f"(c[mt][nt][3])
              : "r"(af[mt][0]), "r"(af[mt][1]), "r"(af[mt][2]), "r"(af[mt][3]),
                "r"(bf[nt][0]), "r"(bf[nt][1]));
        }
    }
    __syncthreads();
  }

  // Epilogue
#pragma unroll
  for (int mt = 0; mt < 2; mt++) {
    int mrow = m0 + wm0 + mt * 16 + lr8;
#pragma unroll
    for (int nt = 0; nt < 8; nt++) {
      int col = n0 + wn0 + nt * 8 + lq * 2;
      *(float2*)(C + (long)mrow * N + col) = make_float2(c[mt][nt][0], c[mt][nt][1]);
      *(float2*)(C + (long)(mrow + 8) * N + col) = make_float2(c[mt][nt][2], c[mt][nt][3]);
    }
  }
}

// ---------------------------------------------------------------------------
// Repack K/V projections [b*S, g*64+d] -> keys/values [b, g, s, d]
// ---------------------------------------------------------------------------
__global__ __launch_bounds__(256) void transpose_kv(
    const float* __restrict__ Kb, const float* __restrict__ Vb,
    float* __restrict__ keys, float* __restrict__ values) {
  int idx = blockIdx.x * blockDim.x + threadIdx.x;     // float4 granularity
  constexpr int total4 = kB * kNKV * kS * kHD / 4;     // 524288
  if (idx >= total4) return;
  int e = idx * 4;
  int d = e & 63;
  int s = (e >> 6) & (kS - 1);
  int g = (e >> 17) & (kNKV - 1);
  int b = e >> 20;
  int src = (b * kS + s) * kKV + g * kHD + d;
  ((float4*)keys)[idx]   = *(const float4*)(Kb + src);
  ((float4*)values)[idx] = *(const float4*)(Vb + src);
}

// ---------------------------------------------------------------------------
// Flash attention, fp32 (unchanged this round; next target).
// ---------------------------------------------------------------------------
__global__ __launch_bounds__(256) void attn_kernel(
    const float* __restrict__ Q, const float* __restrict__ Kc,
    const float* __restrict__ Vc, float* __restrict__ Ctx) {
  extern __shared__ float sm[];
  float* Qst = sm;             // [64 d][68]
  float* Kst = Qst + 64 * 68;  // [64 d][68]
  float* Vs  = Kst + 64 * 68;  // [64 k][68]
  float* Ps  = Vs  + 64 * 68;  // [64 q][68]

  const int qt = blockIdx.x;
  const int hb = blockIdx.y;
  const int b = hb >> 5, h = hb & 31, g = h >> 2;
  const int t = threadIdx.x, tx = t & 15, ty = t >> 4;
  const int q0 = qt * 64;

  const float* Qbase = Q  + (b * kS + q0) * kDout + h * kHD;
  const float* Kbase = Kc + (b * kNKV + g) * kS * kHD;
  const float* Vbase = Vc + (b * kNKV + g) * kS * kHD;

  {
    const int d4 = tx * 4;
#pragma unroll
    for (int r = 0; r < 4; r++) {
      int qq = ty + r * 16;
      float4 v = *(const float4*)(Qbase + qq * kDout + d4);
      Qst[(d4 + 0) * 68 + qq] = v.x;
      Qst[(d4 + 1) * 68 + qq] = v.y;
      Qst[(d4 + 2) * 68 + qq] = v.z;
      Qst[(d4 + 3) * 68 + qq] = v.w;
    }
  }

  float acc[4][4] = {};
  float Mr[4] = {-1e30f, -1e30f, -1e30f, -1e30f};
  float Lr[4] = {};

  for (int kt = 0; kt <= qt; kt++) {
    const int k0 = kt * 64;
    const int d4 = tx * 4;
#pragma unroll
    for (int r = 0; r < 4; r++) {
      int kk = ty + r * 16;
      float4 kv = *(const float4*)(Kbase + (k0 + kk) * kHD + d4);
      Kst[(d4 + 0) * 68 + kk] = kv.x;
      Kst[(d4 + 1) * 68 + kk] = kv.y;
      Kst[(d4 + 2) * 68 + kk] = kv.z;
      Kst[(d4 + 3) * 68 + kk] = kv.w;
      float4 vv = *(const float4*)(Vbase + (k0 + kk) * kHD + d4);
      *(float4*)&Vs[kk * 68 + d4] = vv;
    }
    __syncthreads();

    float sreg[4][4] = {};
#pragma unroll 8
    for (int d = 0; d < 64; d++) {
      float4 qv = *(const float4*)&Qst[d * 68 + ty * 4];
      float4 kv = *(const float4*)&Kst[d * 68 + tx * 4];
      float qa[4] = {qv.x, qv.y, qv.z, qv.w};
      float ka[4] = {kv.x, kv.y, kv.z, kv.w};
#pragma unroll
      for (int i = 0; i < 4; i++)
#pragma unroll
        for (int j = 0; j < 4; j++) sreg[i][j] = fmaf(qa[i], ka[j], sreg[i][j]);
    }

#pragma unroll
    for (int i = 0; i < 4; i++)
#pragma unroll
      for (int j = 0; j < 4; j++) {
        float s = sreg[i][j] * 0.125f;
        if (k0 + tx * 4 + j > q0 + ty * 4 + i) s = -1e30f;
        sreg[i][j] = s;
      }

    float ml[4];
#pragma unroll
    for (int i = 0; i < 4; i++)
      ml[i] = fmaxf(fmaxf(sreg[i][0], sreg[i][1]), fmaxf(sreg[i][2], sreg[i][3]));
#pragma unroll
    for (int off = 8; off >= 1; off >>= 1)
#pragma unroll
      for (int i = 0; i < 4; i++)
        ml[i] = fmaxf(ml[i], __shfl_xor_sync(0xffffffffu, ml[i], off));

    float esc[4], pl[4];
#pragma unroll
    for (int i = 0; i < 4; i++) {
      float mn = fmaxf(Mr[i], ml[i]);
      esc[i] = __expf(Mr[i] - mn);
      Mr[i] = mn;
      float s = 0.f;
#pragma unroll
      for (int j = 0; j < 4; j++) {
        float p = __expf(sreg[i][j] - mn);
        sreg[i][j] = p;
        s += p;
      }
      pl[i] = s;
    }
#pragma unroll
    for (int off = 8; off >= 1; off >>= 1)
#pragma unroll
      for (int i = 0; i < 4; i++)
        pl[i] += __shfl_xor_sync(0xffffffffu, pl[i], off);

#pragma unroll
    for (int i = 0; i < 4; i++) {
      Lr[i] = Lr[i] * esc[i] + pl[i];
#pragma unroll
      for (int j = 0; j < 4; j++) acc[i][j] *= esc[i];
      *(float4*)&Ps[(ty * 4 + i) * 68 + tx * 4] =
          make_float4(sreg[i][0], sreg[i][1], sreg[i][2], sreg[i][3]);
    }
    __syncthreads();

#pragma unroll 8
    for (int kk = 0; kk < 64; kk++) {
      float4 vv = *(const float4*)&Vs[kk * 68 + tx * 4];
      float va[4] = {vv.x, vv.y, vv.z, vv.w};
      float pa[4];
#pragma unroll
      for (int i = 0; i < 4; i++) pa[i] = Ps[(ty * 4 + i) * 68 + kk];
#pragma unroll
      for (int i = 0; i < 4; i++)
#pragma unroll
        for (int j = 0; j < 4; j++) acc[i][j] = fmaf(pa[i], va[j], acc[i][j]);
    }
    __syncthreads();
  }

  float* Cb = Ctx + (b * kS + q0) * kDout + h * kHD;
#pragma unroll
  for (int i = 0; i < 4; i++) {
    float inv = 1.f / Lr[i];
    *(float4*)(Cb + (ty * 4 + i) * kDout + tx * 4) =
        make_float4(acc[i][0] * inv, acc[i][1] * inv,
                    acc[i][2] * inv, acc[i][3] * inv);
  }
}

// ---------------------------------------------------------------------------
extern "C" void kernel_launch(void* const* d_in, const int* in_sizes, int n_in,
                              void* d_out, int out_size) {
  const float* x  = (const float*)d_in[0];
  const float* Wq = (const float*)d_in[1];
  const float* Wk = (const float*)d_in[2];
  const float* Wv = (const float*)d_in[3];
  const float* Wo = (const float*)d_in[4];

  float* out    = (float*)d_out;                    // [2,2048,2048]
  float* keys   = out + kM * kDout;                 // [2,8,2048,64]
  float* values = keys + kB * kNKV * kS * kHD;      // [2,8,2048,64]

  float *qb, *kb, *vb, *cb;
  cudaGetSymbolAddress((void**)&qb, g_Q);
  cudaGetSymbolAddress((void**)&kb, g_Kp);
  cudaGetSymbolAddress((void**)&vb, g_Vp);
  cudaGetSymbolAddress((void**)&cb, g_Ctx);

  dim3 blk(256);
  constexpr int kGemmSmem = 4 * 128 * 36 * (int)sizeof(float);  // 73728 B
  static bool attr_set = false;
  if (!attr_set) {
    cudaFuncSetAttribute(gemm_tf32_nt, cudaFuncAttributeMaxDynamicSharedMemorySize, kGemmSmem);
    attr_set = true;
  }

  // Projections (TF32 tensor cores)
  gemm_tf32_nt<<<dim3(kDout / 128, kM / 128), blk, kGemmSmem>>>(x, Wq, qb, kM, kDout, kDin);
  gemm_tf32_nt<<<dim3(kKV / 128, kM / 128), blk, kGemmSmem>>>(x, Wk, kb, kM, kKV, kDin);
  gemm_tf32_nt<<<dim3(kKV / 128, kM / 128), blk, kGemmSmem>>>(x, Wv, vb, kM, kKV, kDin);
  // Emit keys/values outputs (also the attention-side K/V layout)
  transpose_kv<<<(kB * kNKV * kS * kHD / 4 + 255) / 256, blk>>>(kb, vb, keys, values);
  // Attention (fp32)
  constexpr int kSmem = 4 * 64 * 68 * (int)sizeof(float);  // 69632 B
  cudaFuncSetAttribute(attn_kernel, cudaFuncAttributeMaxDynamicSharedMemorySize, kSmem);
  attn_kernel<<<dim3(kS / 64, kB * kNH), blk, kSmem>>>(qb, keys, values, cb);
  // Output projection
  gemm_tf32_nt<<<dim3(kDout / 128, kM / 128), blk, kGemmSmem>>>(cb, Wo, out, kM, kDout, kDin);
}

// round 4
// speedup vs baseline: 3.0787x; 1.5109x over previous
#include <cuda_runtime.h>
#include <cstdint>

// Problem constants
namespace {
constexpr int kB   = 2;
constexpr int kS   = 2048;
constexpr int kDin = 2048;
constexpr int kNH  = 32;
constexpr int kNKV = 8;
constexpr int kHD  = 64;
constexpr int kDout = 2048;           // kNH * kHD
constexpr int kM   = kB * kS;         // 4096 rows
constexpr int kKV  = kNKV * kHD;      // 512
}

// Scratch (static device arrays; cudaMalloc is forbidden)
__device__ float g_Q[kM * kDout];     // 32 MB
__device__ float g_Kp[kM * kKV];      // 8 MB
__device__ float g_Vp[kM * kKV];      // 8 MB
__device__ float g_Ctx[kM * kDout];   // 32 MB

__device__ __forceinline__ uint32_t f2tf32(float f) {
  uint32_t u;
  asm("cvt.rna.tf32.f32 %0, %1;" : "=r"(u) : "f"(f));
  return u;
}

__device__ __forceinline__ void cp_async16(uint32_t smem_addr, const void* gptr) {
  asm volatile("cp.async.cg.shared.global [%0], [%1], 16;" :: "r"(smem_addr), "l"(gptr));
}

__device__ __forceinline__ void mma_tf32(float* c, const uint32_t* a, const uint32_t* b) {
  asm volatile(
      "mma.sync.aligned.m16n8k8.row.col.f32.tf32.tf32.f32 "
      "{%0,%1,%2,%3}, {%4,%5,%6,%7}, {%8,%9}, {%0,%1,%2,%3};"
      : "+f"(c[0]), "+f"(c[1]), "+f"(c[2]), "+f"(c[3])
      : "r"(a[0]), "r"(a[1]), "r"(a[2]), "r"(a[3]), "r"(b[0]), "r"(b[1]));
}

// ---------------------------------------------------------------------------
// TF32 tensor-core GEMM: C[M,N] = A[M,K] @ B[N,K]^T (both K-contiguous).
// ---------------------------------------------------------------------------
__global__ __launch_bounds__(256) void gemm_tf32_nt(
    const float* __restrict__ A, const float* __restrict__ Bw,
    float* __restrict__ C, int M, int N, int K) {
  constexpr int BM = 128, BN = 128, BK = 32, LD = 36;
  extern __shared__ float smem[];
  float* As = smem;                 // [2][BM][LD]
  float* Bs = smem + 2 * BM * LD;   // [2][BN][LD]

  const int m0 = blockIdx.y * BM, n0 = blockIdx.x * BN;
  const int t = threadIdx.x;
  const int lane = t & 31, w = t >> 5;
  const int wm0 = (w & 3) * 32;
  const int wn0 = (w >> 2) * 64;
  const int lq = lane & 3;
  const int lr8 = lane >> 2;

  const int grow = t >> 3;
  const int gk4  = (t & 7) * 4;

  const float* Agp = A  + (m0 + grow) * (long)K + gk4;
  const float* Bgp = Bw + (n0 + grow) * (long)K + gk4;

  uint32_t sA = (uint32_t)__cvta_generic_to_shared(As);
  uint32_t sB = (uint32_t)__cvta_generic_to_shared(Bs);

  auto load_stage = [&](int buf, int k0) {
    uint32_t abase = sA + (uint32_t)(buf * BM * LD) * 4u;
    uint32_t bbase = sB + (uint32_t)(buf * BN * LD) * 4u;
#pragma unroll
    for (int s = 0; s < 4; s++) {
      int row = grow + s * 32;
      cp_async16(abase + (uint32_t)(row * LD + gk4) * 4u, Agp + (long)s * 32 * K + k0);
      cp_async16(bbase + (uint32_t)(row * LD + gk4) * 4u, Bgp + (long)s * 32 * K + k0);
    }
    asm volatile("cp.async.commit_group;" ::: "memory");
  };

  float c[2][8][4];
#pragma unroll
  for (int i = 0; i < 2; i++)
#pragma unroll
    for (int j = 0; j < 8; j++)
#pragma unroll
      for (int r = 0; r < 4; r++) c[i][j][r] = 0.f;

  const int NIT = K / BK;
  load_stage(0, 0);

  for (int it = 0; it < NIT; it++) {
    if (it + 1 < NIT) {
      load_stage((it + 1) & 1, (it + 1) * BK);
      asm volatile("cp.async.wait_group 1;" ::: "memory");
    } else {
      asm volatile("cp.async.wait_group 0;" ::: "memory");
    }
    __syncthreads();

    const float* Ab = As + (it & 1) * BM * LD;
    const float* Bb = Bs + (it & 1) * BN * LD;

#pragma unroll
    for (int ks = 0; ks < 4; ks++) {
      const int kb = ks * 8;
      uint32_t af[2][4], bf[8][2];
#pragma unroll
      for (int mt = 0; mt < 2; mt++) {
        const float* ap = Ab + (wm0 + mt * 16 + lr8) * LD + kb + lq;
        af[mt][0] = f2tf32(ap[0]);
        af[mt][1] = f2tf32(ap[8 * LD]);
        af[mt][2] = f2tf32(ap[4]);
        af[mt][3] = f2tf32(ap[8 * LD + 4]);
      }
#pragma unroll
      for (int nt = 0; nt < 8; nt++) {
        const float* bp = Bb + (wn0 + nt * 8 + lr8) * LD + kb + lq;
        bf[nt][0] = f2tf32(bp[0]);
        bf[nt][1] = f2tf32(bp[4]);
      }
#pragma unroll
      for (int mt = 0; mt < 2; mt++)
#pragma unroll
        for (int nt = 0; nt < 8; nt++) mma_tf32(c[mt][nt], af[mt], bf[nt]);
    }
    __syncthreads();
  }

#pragma unroll
  for (int mt = 0; mt < 2; mt++) {
    int mrow = m0 + wm0 + mt * 16 + lr8;
#pragma unroll
    for (int nt = 0; nt < 8; nt++) {
      int col = n0 + wn0 + nt * 8 + lq * 2;
      *(float2*)(C + (long)mrow * N + col) = make_float2(c[mt][nt][0], c[mt][nt][1]);
      *(float2*)(C + (long)(mrow + 8) * N + col) = make_float2(c[mt][nt][2], c[mt][nt][3]);
    }
  }
}

// ---------------------------------------------------------------------------
// Repack K/V projections [b*S, g*64+d] -> keys/values [b, g, s, d]
// ---------------------------------------------------------------------------
__global__ __launch_bounds__(256) void transpose_kv(
    const float* __restrict__ Kb, const float* __restrict__ Vb,
    float* __restrict__ keys, float* __restrict__ values) {
  int idx = blockIdx.x * blockDim.x + threadIdx.x;
  constexpr int total4 = kB * kNKV * kS * kHD / 4;
  if (idx >= total4) return;
  int e = idx * 4;
  int d = e & 63;
  int s = (e >> 6) & (kS - 1);
  int g = (e >> 17) & (kNKV - 1);
  int b = e >> 20;
  int src = (b * kS + s) * kKV + g * kHD + d;
  ((float4*)keys)[idx]   = *(const float4*)(Kb + src);
  ((float4*)values)[idx] = *(const float4*)(Vb + src);
}

// ---------------------------------------------------------------------------
// Flash attention with TF32 tensor cores.
// Block = 128 threads (4 warps), 128 queries of one (b,h). Warp tile 32x64.
// Smem tiles hold TF32-pre-rounded floats; inner loops are LDS + HMMA only.
// ---------------------------------------------------------------------------
__global__ __launch_bounds__(128) void attn_tf32(
    const float* __restrict__ Q, const float* __restrict__ Kc,
    const float* __restrict__ Vc, float* __restrict__ Ctx) {
  constexpr int LD = 68;
  extern __shared__ float sm[];
  float* Qs = sm;                  // [128][LD] q rows, d cols (scaled, tf32)
  float* Ks = Qs + 128 * LD;       // [64][LD]  k rows, d cols (tf32)
  float* Vs = Ks + 64 * LD;        // [64][LD]  k rows, d cols (tf32)
  float* Ps = Vs + 64 * LD;        // [128][LD] q rows, kpos cols (tf32)

  const int qt = blockIdx.x;       // 0..15
  const int hb = blockIdx.y;       // 0..63
  const int b = hb >> 5, h = hb & 31, g = h >> 2;
  const int t = threadIdx.x, lane = t & 31, w = t >> 5;
  const int wq0 = w * 32;
  const int lq = lane & 3, lr8 = lane >> 2;
  const int q0 = qt * 128;

  const float* Qbase = Q  + (long)(b * kS + q0) * kDout + h * kHD;
  const float* Kbase = Kc + (long)(b * kNKV + g) * kS * kHD;
  const float* Vbase = Vc + (long)(b * kNKV + g) * kS * kHD;

  // Load Q tile: one row per thread, scale by 1/sqrt(64), round to tf32.
  {
    const float* qp = Qbase + (long)t * kDout;
    float* dst = Qs + t * LD;
#pragma unroll
    for (int i = 0; i < 16; i++) {
      float4 v = *(const float4*)(qp + i * 4);
      dst[i * 4 + 0] = __uint_as_float(f2tf32(v.x * 0.125f));
      dst[i * 4 + 1] = __uint_as_float(f2tf32(v.y * 0.125f));
      dst[i * 4 + 2] = __uint_as_float(f2tf32(v.z * 0.125f));
      dst[i * 4 + 3] = __uint_as_float(f2tf32(v.w * 0.125f));
    }
  }

  float out[2][8][4];
#pragma unroll
  for (int mt = 0; mt < 2; mt++)
#pragma unroll
    for (int nt = 0; nt < 8; nt++)
#pragma unroll
      for (int r = 0; r < 4; r++) out[mt][nt][r] = 0.f;
  float mrow[2][2] = {{-1e30f, -1e30f}, {-1e30f, -1e30f}};
  float lrow[2][2] = {{0.f, 0.f}, {0.f, 0.f}};

  const int nkt = 2 * qt + 2;      // K tiles covering causal range
  for (int kt = 0; kt < nkt; kt++) {
    const int k0 = kt * 64;
    // Load K,V tiles (row = t>>1, 8 float4 each), tf32-rounded.
    {
      const int row = t >> 1;
      const int dof = (t & 1) * 32;
      const float* kp = Kbase + (long)(k0 + row) * kHD + dof;
      const float* vp = Vbase + (long)(k0 + row) * kHD + dof;
      float* kd = Ks + row * LD + dof;
      float* vd = Vs + row * LD + dof;
#pragma unroll
      for (int i = 0; i < 8; i++) {
        float4 kv = *(const float4*)(kp + i * 4);
        kd[i * 4 + 0] = __uint_as_float(f2tf32(kv.x));
        kd[i * 4 + 1] = __uint_as_float(f2tf32(kv.y));
        kd[i * 4 + 2] = __uint_as_float(f2tf32(kv.z));
        kd[i * 4 + 3] = __uint_as_float(f2tf32(kv.w));
        float4 vv = *(const float4*)(vp + i * 4);
        vd[i * 4 + 0] = __uint_as_float(f2tf32(vv.x));
        vd[i * 4 + 1] = __uint_as_float(f2tf32(vv.y));
        vd[i * 4 + 2] = __uint_as_float(f2tf32(vv.z));
        vd[i * 4 + 3] = __uint_as_float(f2tf32(vv.w));
      }
    }
    __syncthreads();

    // S = Q K^T
    float sc[2][8][4];
#pragma unroll
    for (int mt = 0; mt < 2; mt++)
#pragma unroll
      for (int nt = 0; nt < 8; nt++)
#pragma unroll
        for (int r = 0; r < 4; r++) sc[mt][nt][r] = 0.f;

#pragma unroll
    for (int ks = 0; ks < 8; ks++) {
      const int kb = ks * 8;
      uint32_t af[2][4], bf[8][2];
#pragma unroll
      for (int mt = 0; mt < 2; mt++) {
        const float* ap = Qs + (wq0 + mt * 16 + lr8) * LD + kb + lq;
        af[mt][0] = __float_as_uint(ap[0]);
        af[mt][1] = __float_as_uint(ap[8 * LD]);
        af[mt][2] = __float_as_uint(ap[4]);
        af[mt][3] = __float_as_uint(ap[8 * LD + 4]);
      }
#pragma unroll
      for (int nt = 0; nt < 8; nt++) {
        const float* bp = Ks + (nt * 8 + lr8) * LD + kb + lq;
        bf[nt][0] = __float_as_uint(bp[0]);
        bf[nt][1] = __float_as_uint(bp[4]);
      }
#pragma unroll
      for (int mt = 0; mt < 2; mt++)
#pragma unroll
        for (int nt = 0; nt < 8; nt++) mma_tf32(sc[mt][nt], af[mt], bf[nt]);
    }

    // Causal mask (warp-uniform skip when tile is fully unmasked)
    if (k0 + 63 > q0 + wq0) {
#pragma unroll
      for (int mt = 0; mt < 2; mt++) {
        int r0 = q0 + wq0 + mt * 16 + lr8;
        int r1 = r0 + 8;
#pragma unroll
        for (int nt = 0; nt < 8; nt++) {
          int col = k0 + nt * 8 + 2 * lq;
          if (col > r0)     sc[mt][nt][0] = -1e30f;
          if (col + 1 > r0) sc[mt][nt][1] = -1e30f;
          if (col > r1)     sc[mt][nt][2] = -1e30f;
          if (col + 1 > r1) sc[mt][nt][3] = -1e30f;
        }
      }
    }

    // Online softmax (rows lr8 / lr8+8 per m-tile; reduce over quad)
#pragma unroll
    for (int mt = 0; mt < 2; mt++) {
      float mx0 = -1e30f, mx1 = -1e30f;
#pragma unroll
      for (int nt = 0; nt < 8; nt++) {
        mx0 = fmaxf(mx0, fmaxf(sc[mt][nt][0], sc[mt][nt][1]));
        mx1 = fmaxf(mx1, fmaxf(sc[mt][nt][2], sc[mt][nt][3]));
      }
      mx0 = fmaxf(mx0, __shfl_xor_sync(0xffffffffu, mx0, 1));
      mx0 = fmaxf(mx0, __shfl_xor_sync(0xffffffffu, mx0, 2));
      mx1 = fmaxf(mx1, __shfl_xor_sync(0xffffffffu, mx1, 1));
      mx1 = fmaxf(mx1, __shfl_xor_sync(0xffffffffu, mx1, 2));

      float mn0 = fmaxf(mrow[mt][0], mx0);
      float mn1 = fmaxf(mrow[mt][1], mx1);
      float e0 = __expf(mrow[mt][0] - mn0);
      float e1 = __expf(mrow[mt][1] - mn1);
      mrow[mt][0] = mn0; mrow[mt][1] = mn1;

      float s0 = 0.f, s1 = 0.f;
      float* pr0 = Ps + (wq0 + mt * 16 + lr8) * LD + 2 * lq;
      float* pr1 = pr0 + 8 * LD;
#pragma unroll
      for (int nt = 0; nt < 8; nt++) {
        float p0 = __uint_as_float(f2tf32(__expf(sc[mt][nt][0] - mn0)));
        float p1 = __uint_as_float(f2tf32(__expf(sc[mt][nt][1] - mn0)));
        float p2 = __uint_as_float(f2tf32(__expf(sc[mt][nt][2] - mn1)));
        float p3 = __uint_as_float(f2tf32(__expf(sc[mt][nt][3] - mn1)));
        s0 += p0 + p1;
        s1 += p2 + p3;
        *(float2*)(pr0 + nt * 8) = make_float2(p0, p1);
        *(float2*)(pr1 + nt * 8) = make_float2(p2, p3);
      }
      s0 += __shfl_xor_sync(0xffffffffu, s0, 1);
      s0 += __shfl_xor_sync(0xffffffffu, s0, 2);
      s1 += __shfl_xor_sync(0xffffffffu, s1, 1);
      s1 += __shfl_xor_sync(0xffffffffu, s1, 2);
      lrow[mt][0] = lrow[mt][0] * e0 + s0;
      lrow[mt][1] = lrow[mt][1] * e1 + s1;
#pragma unroll
      for (int nt = 0; nt < 8; nt++) {
        out[mt][nt][0] *= e0; out[mt][nt][1] *= e0;
        out[mt][nt][2] *= e1; out[mt][nt][3] *= e1;
      }
    }
    __syncwarp();

    // out += P V
#pragma unroll
    for (int ks = 0; ks < 8; ks++) {
      const int kb = ks * 8;
      uint32_t af[2][4], bf[8][2];
#pragma unroll
      for (int mt = 0; mt < 2; mt++) {
        const float* ap = Ps + (wq0 + mt * 16 + lr8) * LD + kb + lq;
        af[mt][0] = __float_as_uint(ap[0]);
        af[mt][1] = __float_as_uint(ap[8 * LD]);
        af[mt][2] = __float_as_uint(ap[4]);
        af[mt][3] = __float_as_uint(ap[8 * LD + 4]);
      }
#pragma unroll
      for (int nt = 0; nt < 8; nt++) {
        const float* vp = Vs + (kb + lq) * LD + nt * 8 + lr8;
        bf[nt][0] = __float_as_uint(vp[0]);
        bf[nt][1] = __float_as_uint(vp[4 * LD]);
      }
#pragma unroll
      for (int mt = 0; mt < 2; mt++)
#pragma unroll
        for (int nt = 0; nt < 8; nt++) mma_tf32(out[mt][nt], af[mt], bf[nt]);
    }
    __syncthreads();
  }

  // Epilogue: normalize and store
  float* Cb = Ctx + (long)(b * kS + q0) * kDout + h * kHD;
#pragma unroll
  for (int mt = 0; mt < 2; mt++) {
    int r0 = wq0 + mt * 16 + lr8;
    float inv0 = 1.f / lrow[mt][0];
    float inv1 = 1.f / lrow[mt][1];
#pragma unroll
    for (int nt = 0; nt < 8; nt++) {
      int col = nt * 8 + 2 * lq;
      *(float2*)(Cb + (long)r0 * kDout + col) =
          make_float2(out[mt][nt][0] * inv0, out[mt][nt][1] * inv0);
      *(float2*)(Cb + (long)(r0 + 8) * kDout + col) =
          make_float2(out[mt][nt][2] * inv1, out[mt][nt][3] * inv1);
    }
  }
}

// ---------------------------------------------------------------------------
extern "C" void kernel_launch(void* const* d_in, const int* in_sizes, int n_in,
                              void* d_out, int out_size) {
  const float* x  = (const float*)d_in[0];
  const float* Wq = (const float*)d_in[1];
  const float* Wk = (const float*)d_in[2];
  const float* Wv = (const float*)d_in[3];
  const float* Wo = (const float*)d_in[4];

  float* out    = (float*)d_out;                    // [2,2048,2048]
  float* keys   = out + kM * kDout;                 // [2,8,2048,64]
  float* values = keys + kB * kNKV * kS * kHD;      // [2,8,2048,64]

  float *qb, *kb, *vb, *cb;
  cudaGetSymbolAddress((void**)&qb, g_Q);
  cudaGetSymbolAddress((void**)&kb, g_Kp);
  cudaGetSymbolAddress((void**)&vb, g_Vp);
  cudaGetSymbolAddress((void**)&cb, g_Ctx);

  constexpr int kGemmSmem = 4 * 128 * 36 * (int)sizeof(float);   // 73728 B
  constexpr int kAttnSmem = (128 + 64 + 64 + 128) * 68 * (int)sizeof(float);  // 104448 B
  static bool attr_set = false;
  if (!attr_set) {
    cudaFuncSetAttribute(gemm_tf32_nt, cudaFuncAttributeMaxDynamicSharedMemorySize, kGemmSmem);
    cudaFuncSetAttribute(attn_tf32, cudaFuncAttributeMaxDynamicSharedMemorySize, kAttnSmem);
    attr_set = true;
  }

  dim3 blk(256);
  // Projections (TF32 tensor cores)
  gemm_tf32_nt<<<dim3(kDout / 128, kM / 128), blk, kGemmSmem>>>(x, Wq, qb, kM, kDout, kDin);
  gemm_tf32_nt<<<dim3(kKV / 128, kM / 128), blk, kGemmSmem>>>(x, Wk, kb, kM, kKV, kDin);
  gemm_tf32_nt<<<dim3(kKV / 128, kM / 128), blk, kGemmSmem>>>(x, Wv, vb, kM, kKV, kDin);
  // Emit keys/values outputs (also the attention-side K/V layout)
  transpose_kv<<<(kB * kNKV * kS * kHD / 4 + 255) / 256, blk>>>(kb, vb, keys, values);
  // Attention (TF32 tensor cores)
  attn_tf32<<<dim3(kS / 128, kB * kNH), dim3(128), kAttnSmem>>>(qb, keys, values, cb);
  // Output projection
  gemm_tf32_nt<<<dim3(kDout / 128, kM / 128), blk, kGemmSmem>>>(cb, Wo, out, kM, kDout, kDin);
}

// round 6
// speedup vs baseline: 3.7296x; 1.2114x over previous
#include <cuda_runtime.h>
#include <cstdint>

// Problem constants
namespace {
constexpr int kB   = 2;
constexpr int kS   = 2048;
constexpr int kDin = 2048;
constexpr int kNH  = 32;
constexpr int kNKV = 8;
constexpr int kHD  = 64;
constexpr int kDout = 2048;           // kNH * kHD
constexpr int kM   = kB * kS;         // 4096 rows
constexpr int kKV  = kNKV * kHD;      // 512
// combined scale: (1/sqrt(64)) * log2(e) so softmax uses raw EX2
constexpr float kQScale = 0.18033688f;
}

// Scratch (static device arrays; cudaMalloc is forbidden)
__device__ float g_Q[kM * kDout];     // 32 MB (pre-scaled, tf32-rounded)
__device__ float g_Kp[kM * kKV];      // 8 MB
__device__ float g_Vp[kM * kKV];      // 8 MB
__device__ float g_Kr[kM * kKV];      // 8 MB (tf32-rounded, [b,g,s,d])
__device__ float g_Vr[kM * kKV];      // 8 MB (tf32-rounded, [b,g,s,d])
__device__ float g_Ctx[kM * kDout];   // 32 MB

__device__ __forceinline__ uint32_t f2tf32(float f) {
  uint32_t u;
  asm("cvt.rna.tf32.f32 %0, %1;" : "=r"(u) : "f"(f));
  return u;
}

__device__ __forceinline__ float fexp2(float x) {
  float y;
  asm("ex2.approx.ftz.f32 %0, %1;" : "=f"(y) : "f"(x));
  return y;
}

__device__ __forceinline__ void cp_async16(uint32_t smem_addr, const void* gptr) {
  asm volatile("cp.async.cg.shared.global [%0], [%1], 16;" :: "r"(smem_addr), "l"(gptr));
}

__device__ __forceinline__ void mma_tf32(float* c, const uint32_t* a, const uint32_t* b) {
  asm volatile(
      "mma.sync.aligned.m16n8k8.row.col.f32.tf32.tf32.f32 "
      "{%0,%1,%2,%3}, {%4,%5,%6,%7}, {%8,%9}, {%0,%1,%2,%3};"
      : "+f"(c[0]), "+f"(c[1]), "+f"(c[2]), "+f"(c[3])
      : "r"(a[0]), "r"(a[1]), "r"(a[2]), "r"(a[3]), "r"(b[0]), "r"(b[1]));
}

// ---------------------------------------------------------------------------
// TF32 tensor-core GEMM: C[M,N] = A[M,K] @ B[N,K]^T (both K-contiguous).
// QMODE 1: epilogue multiplies by kQScale and rounds to tf32 (Q projection).
// ---------------------------------------------------------------------------
template <int QMODE>
__global__ __launch_bounds__(256) void gemm_tf32_nt(
    const float* __restrict__ A, const float* __restrict__ Bw,
    float* __restrict__ C, int M, int N, int K) {
  constexpr int BM = 128, BN = 128, BK = 32, LD = 36;
  extern __shared__ float smem[];
  float* As = smem;                 // [2][BM][LD]
  float* Bs = smem + 2 * BM * LD;   // [2][BN][LD]

  const int m0 = blockIdx.y * BM, n0 = blockIdx.x * BN;
  const int t = threadIdx.x;
  const int lane = t & 31, w = t >> 5;
  const int wm0 = (w & 3) * 32;
  const int wn0 = (w >> 2) * 64;
  const int lq = lane & 3;
  const int lr8 = lane >> 2;

  const int grow = t >> 3;
  const int gk4  = (t & 7) * 4;

  const float* Agp = A  + (m0 + grow) * (long)K + gk4;
  const float* Bgp = Bw + (n0 + grow) * (long)K + gk4;

  uint32_t sA = (uint32_t)__cvta_generic_to_shared(As);
  uint32_t sB = (uint32_t)__cvta_generic_to_shared(Bs);

  auto load_stage = [&](int buf, int k0) {
    uint32_t abase = sA + (uint32_t)(buf * BM * LD) * 4u;
    uint32_t bbase = sB + (uint32_t)(buf * BN * LD) * 4u;
#pragma unroll
    for (int s = 0; s < 4; s++) {
      int row = grow + s * 32;
      cp_async16(abase + (uint32_t)(row * LD + gk4) * 4u, Agp + (long)s * 32 * K + k0);
      cp_async16(bbase + (uint32_t)(row * LD + gk4) * 4u, Bgp + (long)s * 32 * K + k0);
    }
    asm volatile("cp.async.commit_group;" ::: "memory");
  };

  float c[2][8][4];
#pragma unroll
  for (int i = 0; i < 2; i++)
#pragma unroll
    for (int j = 0; j < 8; j++)
#pragma unroll
      for (int r = 0; r < 4; r++) c[i][j][r] = 0.f;

  const int NIT = K / BK;
  load_stage(0, 0);

  for (int it = 0; it < NIT; it++) {
    if (it + 1 < NIT) {
      load_stage((it + 1) & 1, (it + 1) * BK);
      asm volatile("cp.async.wait_group 1;" ::: "memory");
    } else {
      asm volatile("cp.async.wait_group 0;" ::: "memory");
    }
    __syncthreads();

    const float* Ab = As + (it & 1) * BM * LD;
    const float* Bb = Bs + (it & 1) * BN * LD;

#pragma unroll
    for (int ks = 0; ks < 4; ks++) {
      const int kb = ks * 8;
      uint32_t af[2][4], bf[8][2];
#pragma unroll
      for (int mt = 0; mt < 2; mt++) {
        const float* ap = Ab + (wm0 + mt * 16 + lr8) * LD + kb + lq;
        af[mt][0] = f2tf32(ap[0]);
        af[mt][1] = f2tf32(ap[8 * LD]);
        af[mt][2] = f2tf32(ap[4]);
        af[mt][3] = f2tf32(ap[8 * LD + 4]);
      }
#pragma unroll
      for (int nt = 0; nt < 8; nt++) {
        const float* bp = Bb + (wn0 + nt * 8 + lr8) * LD + kb + lq;
        bf[nt][0] = f2tf32(bp[0]);
        bf[nt][1] = f2tf32(bp[4]);
      }
#pragma unroll
      for (int mt = 0; mt < 2; mt++)
#pragma unroll
        for (int nt = 0; nt < 8; nt++) mma_tf32(c[mt][nt], af[mt], bf[nt]);
    }
    __syncthreads();
  }

#pragma unroll
  for (int mt = 0; mt < 2; mt++) {
    int mrow = m0 + wm0 + mt * 16 + lr8;
#pragma unroll
    for (int nt = 0; nt < 8; nt++) {
      int col = n0 + wn0 + nt * 8 + lq * 2;
      if (QMODE == 1) {
#pragma unroll
        for (int r = 0; r < 4; r++) c[mt][nt][r] = __uint_as_float(f2tf32(c[mt][nt][r] * kQScale));
      }
      *(float2*)(C + (long)mrow * N + col) = make_float2(c[mt][nt][0], c[mt][nt][1]);
      *(float2*)(C + (long)(mrow + 8) * N + col) = make_float2(c[mt][nt][2], c[mt][nt][3]);
    }
  }
}

// ---------------------------------------------------------------------------
// Repack K/V projections [b*S, g*64+d] -> keys/values [b, g, s, d] (exact)
// plus tf32-rounded copies Kr/Vr for the attention kernel.
// ---------------------------------------------------------------------------
__global__ __launch_bounds__(256) void transpose_kv(
    const float* __restrict__ Kb, const float* __restrict__ Vb,
    float* __restrict__ keys, float* __restrict__ values,
    float* __restrict__ Kr, float* __restrict__ Vr) {
  int idx = blockIdx.x * blockDim.x + threadIdx.x;
  constexpr int total4 = kB * kNKV * kS * kHD / 4;
  if (idx >= total4) return;
  int e = idx * 4;
  int d = e & 63;
  int s = (e >> 6) & (kS - 1);
  int g = (e >> 17) & (kNKV - 1);
  int b = e >> 20;
  int src = (b * kS + s) * kKV + g * kHD + d;
  float4 kv = *(const float4*)(Kb + src);
  float4 vv = *(const float4*)(Vb + src);
  ((float4*)keys)[idx]   = kv;
  ((float4*)values)[idx] = vv;
  float4 kr = make_float4(__uint_as_float(f2tf32(kv.x)), __uint_as_float(f2tf32(kv.y)),
                          __uint_as_float(f2tf32(kv.z)), __uint_as_float(f2tf32(kv.w)));
  float4 vr = make_float4(__uint_as_float(f2tf32(vv.x)), __uint_as_float(f2tf32(vv.y)),
                          __uint_as_float(f2tf32(vv.z)), __uint_as_float(f2tf32(vv.w)));
  ((float4*)Kr)[idx] = kr;
  ((float4*)Vr)[idx] = vr;
}

// ---------------------------------------------------------------------------
// Flash attention, TF32 mma.sync, cp.async-pipelined K/V tiles.
// Block = 128 threads (4 warps), 128 queries of one (b,h). Warp tile 32x64.
// All operands pre-rounded to tf32 in gmem; inner loop is LDS + MMA only.
// ---------------------------------------------------------------------------
__global__ __launch_bounds__(128) void attn_tf32(
    const float* __restrict__ Q, const float* __restrict__ Kc,
    const float* __restrict__ Vc, float* __restrict__ Ctx) {
  constexpr int LD = 68, LDV = 72;
  extern __shared__ float sm[];
  float* Qs = sm;                   // [128][LD]
  float* Ks = Qs + 128 * LD;        // [64][LD]
  float* Vs = Ks + 64 * LD;         // [64][LDV]
  float* Ps = Vs + 64 * LDV;        // [128][LD]

  const int qt = gridDim.x - 1 - blockIdx.x;   // heavy blocks first
  const int hb = blockIdx.y;
  const int b = hb >> 5, h = hb & 31, g = h >> 2;
  const int t = threadIdx.x, lane = t & 31, w = t >> 5;
  const int wq0 = w * 32;
  const int lq = lane & 3, lr8 = lane >> 2;
  const int q0 = qt * 128;

  const float* Qbase = Q  + (long)(b * kS + q0) * kDout + h * kHD;
  const float* Kbase = Kc + (long)(b * kNKV + g) * kS * kHD;
  const float* Vbase = Vc + (long)(b * kNKV + g) * kS * kHD;

  const uint32_t sK = (uint32_t)__cvta_generic_to_shared(Ks);
  const uint32_t sV = (uint32_t)__cvta_generic_to_shared(Vs);

  // Each thread copies 8 16B chunks per tile (64 rows x 16 chunks = 1024).
  const int ch_r = t >> 4;          // base row group: rows ch_r + 8*i? use chunk id
  (void)ch_r;
  auto issue_K = [&](int k0) {
#pragma unroll
    for (int i = 0; i < 8; i++) {
      int chunk = t + i * 128;
      int r = chunk >> 4, cc = chunk & 15;
      cp_async16(sK + (uint32_t)(r * LD + cc * 4) * 4u, Kbase + (long)(k0 + r) * kHD + cc * 4);
    }
    asm volatile("cp.async.commit_group;" ::: "memory");
  };
  auto issue_V = [&](int k0) {
#pragma unroll
    for (int i = 0; i < 8; i++) {
      int chunk = t + i * 128;
      int r = chunk >> 4, cc = chunk & 15;
      cp_async16(sV + (uint32_t)(r * LDV + cc * 4) * 4u, Vbase + (long)(k0 + r) * kHD + cc * 4);
    }
    asm volatile("cp.async.commit_group;" ::: "memory");
  };

  issue_K(0);
  issue_V(0);

  {  // Q tile: pre-scaled + tf32-rounded in gmem -> straight copy
    const float* qp = Qbase + (long)t * kDout;
    float* dst = Qs + t * LD;
#pragma unroll
    for (int i = 0; i < 16; i++) *(float4*)(dst + i * 4) = *(const float4*)(qp + i * 4);
  }

  float out[2][8][4];
#pragma unroll
  for (int mt = 0; mt < 2; mt++)
#pragma unroll
    for (int nt = 0; nt < 8; nt++)
#pragma unroll
      for (int r = 0; r < 4; r++) out[mt][nt][r] = 0.f;
  float mrow[2][2] = {{-1e30f, -1e30f}, {-1e30f, -1e30f}};
  float lrow[2][2] = {{0.f, 0.f}, {0.f, 0.f}};

  const int nkt = 2 * qt + 2;
  for (int kt = 0; kt < nkt; kt++) {
    const int k0 = kt * 64;

    // K[kt] ready (V[kt] may still be in flight)
    asm volatile("cp.async.wait_group 1;" ::: "memory");
    __syncthreads();

    // S = Q K^T
    float sc[2][8][4];
#pragma unroll
    for (int mt = 0; mt < 2; mt++)
#pragma unroll
      for (int nt = 0; nt < 8; nt++)
#pragma unroll
        for (int r = 0; r < 4; r++) sc[mt][nt][r] = 0.f;

#pragma unroll
    for (int ks = 0; ks < 8; ks++) {
      const int kb = ks * 8;
      uint32_t af[2][4], bf[8][2];
#pragma unroll
      for (int mt = 0; mt < 2; mt++) {
        const float* ap = Qs + (wq0 + mt * 16 + lr8) * LD + kb + lq;
        af[mt][0] = __float_as_uint(ap[0]);
        af[mt][1] = __float_as_uint(ap[8 * LD]);
        af[mt][2] = __float_as_uint(ap[4]);
        af[mt][3] = __float_as_uint(ap[8 * LD + 4]);
      }
#pragma unroll
      for (int nt = 0; nt < 8; nt++) {
        const float* bp = Ks + (nt * 8 + lr8) * LD + kb + lq;
        bf[nt][0] = __float_as_uint(bp[0]);
        bf[nt][1] = __float_as_uint(bp[4]);
      }
#pragma unroll
      for (int mt = 0; mt < 2; mt++)
#pragma unroll
        for (int nt = 0; nt < 8; nt++) mma_tf32(sc[mt][nt], af[mt], bf[nt]);
    }

    // V[kt] ready; all warps past QK^T -> Ks free for the next tile
    asm volatile("cp.async.wait_group 0;" ::: "memory");
    __syncthreads();
    if (kt + 1 < nkt) issue_K(k0 + 64);

    // Causal mask (warp-uniform skip when tile is fully unmasked)
    if (k0 + 63 > q0 + wq0) {
#pragma unroll
      for (int mt = 0; mt < 2; mt++) {
        int r0 = q0 + wq0 + mt * 16 + lr8;
        int r1 = r0 + 8;
#pragma unroll
        for (int nt = 0; nt < 8; nt++) {
          int col = k0 + nt * 8 + 2 * lq;
          if (col > r0)     sc[mt][nt][0] = -1e30f;
          if (col + 1 > r0) sc[mt][nt][1] = -1e30f;
          if (col > r1)     sc[mt][nt][2] = -1e30f;
          if (col + 1 > r1) sc[mt][nt][3] = -1e30f;
        }
      }
    }

    // Online softmax (scores are in log2 domain; EX2 throughout)
#pragma unroll
    for (int mt = 0; mt < 2; mt++) {
      float mx0 = -1e30f, mx1 = -1e30f;
#pragma unroll
      for (int nt = 0; nt < 8; nt++) {
        mx0 = fmaxf(mx0, fmaxf(sc[mt][nt][0], sc[mt][nt][1]));
        mx1 = fmaxf(mx1, fmaxf(sc[mt][nt][2], sc[mt][nt][3]));
      }
      mx0 = fmaxf(mx0, __shfl_xor_sync(0xffffffffu, mx0, 1));
      mx0 = fmaxf(mx0, __shfl_xor_sync(0xffffffffu, mx0, 2));
      mx1 = fmaxf(mx1, __shfl_xor_sync(0xffffffffu, mx1, 1));
      mx1 = fmaxf(mx1, __shfl_xor_sync(0xffffffffu, mx1, 2));

      float mn0 = fmaxf(mrow[mt][0], mx0);
      float mn1 = fmaxf(mrow[mt][1], mx1);
      float e0 = fexp2(mrow[mt][0] - mn0);
      float e1 = fexp2(mrow[mt][1] - mn1);
      mrow[mt][0] = mn0; mrow[mt][1] = mn1;

      float s0 = 0.f, s1 = 0.f;
      float* pr0 = Ps + (wq0 + mt * 16 + lr8) * LD + 2 * lq;
      float* pr1 = pr0 + 8 * LD;
#pragma unroll
      for (int nt = 0; nt < 8; nt++) {
        float p0 = __uint_as_float(f2tf32(fexp2(sc[mt][nt][0] - mn0)));
        float p1 = __uint_as_float(f2tf32(fexp2(sc[mt][nt][1] - mn0)));
        float p2 = __uint_as_float(f2tf32(fexp2(sc[mt][nt][2] - mn1)));
        float p3 = __uint_as_float(f2tf32(fexp2(sc[mt][nt][3] - mn1)));
        s0 += p0 + p1;
        s1 += p2 + p3;
        *(float2*)(pr0 + nt * 8) = make_float2(p0, p1);
        *(float2*)(pr1 + nt * 8) = make_float2(p2, p3);
      }
      s0 += __shfl_xor_sync(0xffffffffu, s0, 1);
      s0 += __shfl_xor_sync(0xffffffffu, s0, 2);
      s1 += __shfl_xor_sync(0xffffffffu, s1, 1);
      s1 += __shfl_xor_sync(0xffffffffu, s1, 2);
      lrow[mt][0] = lrow[mt][0] * e0 + s0;
      lrow[mt][1] = lrow[mt][1] * e1 + s1;
#pragma unroll
      for (int nt = 0; nt < 8; nt++) {
        out[mt][nt][0] *= e0; out[mt][nt][1] *= e0;
        out[mt][nt][2] *= e1; out[mt][nt][3] *= e1;
      }
    }
    __syncwarp();

    // out += P V
#pragma unroll
    for (int ks = 0; ks < 8; ks++) {
      const int kb = ks * 8;
      uint32_t af[2][4], bf[8][2];
#pragma unroll
      for (int mt = 0; mt < 2; mt++) {
        const float* ap = Ps + (wq0 + mt * 16 + lr8) * LD + kb + lq;
        af[mt][0] = __float_as_uint(ap[0]);
        af[mt][1] = __float_as_uint(ap[8 * LD]);
        af[mt][2] = __float_as_uint(ap[4]);
        af[mt][3] = __float_as_uint(ap[8 * LD + 4]);
      }
#pragma unroll
      for (int nt = 0; nt < 8; nt++) {
        const float* vp = Vs + (kb + lq) * LDV + nt * 8 + lr8;
        bf[nt][0] = __float_as_uint(vp[0]);
        bf[nt][1] = __float_as_uint(vp[4 * LDV]);
      }
#pragma unroll
      for (int mt = 0; mt < 2; mt++)
#pragma unroll
        for (int nt = 0; nt < 8; nt++) mma_tf32(out[mt][nt], af[mt], bf[nt]);
    }
    __syncthreads();   // all warps done with Vs, Ps
    if (kt + 1 < nkt) issue_V(k0 + 64);
  }

  // Epilogue: normalize and store ctx
  float* Cb = Ctx + (long)(b * kS + q0) * kDout + h * kHD;
#pragma unroll
  for (int mt = 0; mt < 2; mt++) {
    int r0 = wq0 + mt * 16 + lr8;
    float inv0 = 1.f / lrow[mt][0];
    float inv1 = 1.f / lrow[mt][1];
#pragma unroll
    for (int nt = 0; nt < 8; nt++) {
      int col = nt * 8 + 2 * lq;
      *(float2*)(Cb + (long)r0 * kDout + col) =
          make_float2(out[mt][nt][0] * inv0, out[mt][nt][1] * inv0);
      *(float2*)(Cb + (long)(r0 + 8) * kDout + col) =
          make_float2(out[mt][nt][2] * inv1, out[mt][nt][3] * inv1);
    }
  }
}

// ---------------------------------------------------------------------------
extern "C" void kernel_launch(void* const* d_in, const int* in_sizes, int n_in,
                              void* d_out, int out_size) {
  const float* x  = (const float*)d_in[0];
  const float* Wq = (const float*)d_in[1];
  const float* Wk = (const float*)d_in[2];
  const float* Wv = (const float*)d_in[3];
  const float* Wo = (const float*)d_in[4];

  float* out    = (float*)d_out;                    // [2,2048,2048]
  float* keys   = out + kM * kDout;                 // [2,8,2048,64]
  float* values = keys + kB * kNKV * kS * kHD;      // [2,8,2048,64]

  float *qb, *kb, *vb, *kr, *vr, *cb;
  cudaGetSymbolAddress((void**)&qb, g_Q);
  cudaGetSymbolAddress((void**)&kb, g_Kp);
  cudaGetSymbolAddress((void**)&vb, g_Vp);
  cudaGetSymbolAddress((void**)&kr, g_Kr);
  cudaGetSymbolAddress((void**)&vr, g_Vr);
  cudaGetSymbolAddress((void**)&cb, g_Ctx);

  constexpr int kGemmSmem = 4 * 128 * 36 * (int)sizeof(float);   // 73728 B
  constexpr int kAttnSmem =
      (128 * 68 + 64 * 68 + 64 * 72 + 128 * 68) * (int)sizeof(float);  // 105472 B
  static bool attr_set = false;
  if (!attr_set) {
    cudaFuncSetAttribute(gemm_tf32_nt<0>, cudaFuncAttributeMaxDynamicSharedMemorySize, kGemmSmem);
    cudaFuncSetAttribute(gemm_tf32_nt<1>, cudaFuncAttributeMaxDynamicSharedMemorySize, kGemmSmem);
    cudaFuncSetAttribute(attn_tf32, cudaFuncAttributeMaxDynamicSharedMemorySize, kAttnSmem);
    attr_set = true;
  }

  dim3 blk(256);
  // Projections (TF32 tensor cores); Q epilogue pre-scales + rounds
  gemm_tf32_nt<1><<<dim3(kDout / 128, kM / 128), blk, kGemmSmem>>>(x, Wq, qb, kM, kDout, kDin);
  gemm_tf32_nt<0><<<dim3(kKV / 128, kM / 128), blk, kGemmSmem>>>(x, Wk, kb, kM, kKV, kDin);
  gemm_tf32_nt<0><<<dim3(kKV / 128, kM / 128), blk, kGemmSmem>>>(x, Wv, vb, kM, kKV, kDin);
  // keys/values outputs (exact) + tf32-rounded attention copies
  transpose_kv<<<(kB * kNKV * kS * kHD / 4 + 255) / 256, blk>>>(kb, vb, keys, values, kr, vr);
  // Attention (TF32 tensor cores, cp.async pipelined)
  attn_tf32<<<dim3(kS / 128, kB * kNH), dim3(128), kAttnSmem>>>(qb, kr, vr, cb);
  // Output projection
  gemm_tf32_nt<0><<<dim3(kDout / 128, kM / 128), blk, kGemmSmem>>>(cb, Wo, out, kM, kDout, kDin);
}

// round 7
// speedup vs baseline: 3.9321x; 1.0543x over previous
#include <cuda_runtime.h>
#include <cstdint>

// Problem constants
namespace {
constexpr int kB   = 2;
constexpr int kS   = 2048;
constexpr int kDin = 2048;
constexpr int kNH  = 32;
constexpr int kNKV = 8;
constexpr int kHD  = 64;
constexpr int kDout = 2048;           // kNH * kHD
constexpr int kM   = kB * kS;         // 4096 rows
constexpr int kKV  = kNKV * kHD;      // 512
// combined scale: (1/sqrt(64)) * log2(e) so softmax uses raw EX2
constexpr float kQScale = 0.18033688f;
}

// Scratch (static device arrays; cudaMalloc is forbidden)
__device__ float g_Q[kM * kDout];     // 32 MB (pre-scaled, tf32-rounded, [b,h,s,d])
__device__ float g_Kr[kM * kKV];      // 8 MB (tf32-rounded, [b,g,s,d])
__device__ float g_Vr[kM * kKV];      // 8 MB (tf32-rounded, [b,g,s,d])
__device__ float g_Ctx[kM * kDout];   // 32 MB

__device__ __forceinline__ uint32_t f2tf32(float f) {
  uint32_t u;
  asm("cvt.rna.tf32.f32 %0, %1;" : "=r"(u) : "f"(f));
  return u;
}
__device__ __forceinline__ float rtf(float f) { return __uint_as_float(f2tf32(f)); }

__device__ __forceinline__ float fexp2(float x) {
  float y;
  asm("ex2.approx.ftz.f32 %0, %1;" : "=f"(y) : "f"(x));
  return y;
}

__device__ __forceinline__ void cp_async16(uint32_t smem_addr, const void* gptr) {
  asm volatile("cp.async.cg.shared.global [%0], [%1], 16;" :: "r"(smem_addr), "l"(gptr));
}

__device__ __forceinline__ void mma_tf32(float* c, const uint32_t* a, const uint32_t* b) {
  asm volatile(
      "mma.sync.aligned.m16n8k8.row.col.f32.tf32.tf32.f32 "
      "{%0,%1,%2,%3}, {%4,%5,%6,%7}, {%8,%9}, {%0,%1,%2,%3};"
      : "+f"(c[0]), "+f"(c[1]), "+f"(c[2]), "+f"(c[3])
      : "r"(a[0]), "r"(a[1]), "r"(a[2]), "r"(a[3]), "r"(b[0]), "r"(b[1]));
}

// ---------------------------------------------------------------------------
// TF32 GEMM mainloop shared by both GEMM kernels (128x128x32, double buffer).
// Returns accumulators in c[2][8][4].
// ---------------------------------------------------------------------------
struct GemmCtx {
  int m0, n0, wm0, wn0, lq, lr8;
};

template <typename Epi>
__device__ __forceinline__ void gemm_body(
    const float* __restrict__ A, const float* __restrict__ Bw,
    int K, float* smem, Epi&& epilogue) {
  constexpr int BM = 128, BN = 128, BK = 32, LD = 36;
  float* As = smem;
  float* Bs = smem + 2 * BM * LD;

  const int m0 = blockIdx.y * BM;
  const int t = threadIdx.x;
  const int lane = t & 31, w = t >> 5;
  const int wm0 = (w & 3) * 32;
  const int wn0 = (w >> 2) * 64;
  const int lq = lane & 3;
  const int lr8 = lane >> 2;
  const int grow = t >> 3;
  const int gk4  = (t & 7) * 4;

  const float* Agp = A  + (m0 + grow) * (long)K + gk4;
  const float* Bgp = Bw + grow * (long)K + gk4;   // n0 pre-applied by caller

  uint32_t sA = (uint32_t)__cvta_generic_to_shared(As);
  uint32_t sB = (uint32_t)__cvta_generic_to_shared(Bs);

  auto load_stage = [&](int buf, int k0) {
    uint32_t abase = sA + (uint32_t)(buf * BM * LD) * 4u;
    uint32_t bbase = sB + (uint32_t)(buf * BN * LD) * 4u;
#pragma unroll
    for (int s = 0; s < 4; s++) {
      int row = grow + s * 32;
      cp_async16(abase + (uint32_t)(row * LD + gk4) * 4u, Agp + (long)s * 32 * K + k0);
      cp_async16(bbase + (uint32_t)(row * LD + gk4) * 4u, Bgp + (long)s * 32 * K + k0);
    }
    asm volatile("cp.async.commit_group;" ::: "memory");
  };

  float c[2][8][4];
#pragma unroll
  for (int i = 0; i < 2; i++)
#pragma unroll
    for (int j = 0; j < 8; j++)
#pragma unroll
      for (int r = 0; r < 4; r++) c[i][j][r] = 0.f;

  const int NIT = K / BK;
  load_stage(0, 0);

  for (int it = 0; it < NIT; it++) {
    if (it + 1 < NIT) {
      load_stage((it + 1) & 1, (it + 1) * BK);
      asm volatile("cp.async.wait_group 1;" ::: "memory");
    } else {
      asm volatile("cp.async.wait_group 0;" ::: "memory");
    }
    __syncthreads();

    const float* Ab = As + (it & 1) * BM * LD;
    const float* Bb = Bs + (it & 1) * BN * LD;

#pragma unroll
    for (int ks = 0; ks < 4; ks++) {
      const int kb = ks * 8;
      uint32_t af[2][4], bf[8][2];
#pragma unroll
      for (int mt = 0; mt < 2; mt++) {
        const float* ap = Ab + (wm0 + mt * 16 + lr8) * LD + kb + lq;
        af[mt][0] = f2tf32(ap[0]);
        af[mt][1] = f2tf32(ap[8 * LD]);
        af[mt][2] = f2tf32(ap[4]);
        af[mt][3] = f2tf32(ap[8 * LD + 4]);
      }
#pragma unroll
      for (int nt = 0; nt < 8; nt++) {
        const float* bp = Bb + (wn0 + nt * 8 + lr8) * LD + kb + lq;
        bf[nt][0] = f2tf32(bp[0]);
        bf[nt][1] = f2tf32(bp[4]);
      }
#pragma unroll
      for (int mt = 0; mt < 2; mt++)
#pragma unroll
        for (int nt = 0; nt < 8; nt++) mma_tf32(c[mt][nt], af[mt], bf[nt]);
    }
    __syncthreads();
  }

  GemmCtx ctx{m0, 0, wm0, wn0, lq, lr8};
  epilogue(ctx, c);
}

// ---------------------------------------------------------------------------
// Fused Q/K/V projection. grid = (24, 32):
//   blockIdx.x  0..15 -> Q n-tile (n0 = x*128)      epilogue: scale+round -> g_Q [b,h,s,d]
//   blockIdx.x 16..19 -> K n-tile (n0 = (x-16)*128) epilogue: keys exact + Kr rounded [b,g,s,d]
//   blockIdx.x 20..23 -> V n-tile                   epilogue: values exact + Vr rounded
// ---------------------------------------------------------------------------
__global__ __launch_bounds__(256) void proj_qkv(
    const float* __restrict__ x, const float* __restrict__ Wq,
    const float* __restrict__ Wk, const float* __restrict__ Wv,
    float* __restrict__ Qo, float* __restrict__ keys, float* __restrict__ values,
    float* __restrict__ Kr, float* __restrict__ Vr) {
  extern __shared__ float smem[];
  const int bx = blockIdx.x;
  const float* Bw;
  int n0, which;
  if (bx < 16)      { Bw = Wq; n0 = bx * 128;        which = 0; }
  else if (bx < 20) { Bw = Wk; n0 = (bx - 16) * 128; which = 1; }
  else              { Bw = Wv; n0 = (bx - 20) * 128; which = 2; }

  gemm_body(x, Bw + (long)n0 * kDin, kDin, smem,
    [&](const GemmCtx& g, float c[2][8][4]) {
      float* ex = (which == 1) ? keys : values;
      float* rd = (which == 1) ? Kr : Vr;
#pragma unroll
      for (int mt = 0; mt < 2; mt++) {
        int mrow = g.m0 + g.wm0 + mt * 16 + g.lr8;
        int b = mrow >> 11, s = mrow & 2047;
#pragma unroll
        for (int nt = 0; nt < 8; nt++) {
          int coln = n0 + g.wn0 + nt * 8 + g.lq * 2;
          int head = coln >> 6, d = coln & 63;
          if (which == 0) {
            long dst = ((long)(b * kNH + head) * kS + s) * kHD + d;
            *(float2*)(Qo + dst) =
                make_float2(rtf(c[mt][nt][0] * kQScale), rtf(c[mt][nt][1] * kQScale));
            *(float2*)(Qo + dst + 8 * kHD) =
                make_float2(rtf(c[mt][nt][2] * kQScale), rtf(c[mt][nt][3] * kQScale));
          } else {
            long dst = ((long)(b * kNKV + head) * kS + s) * kHD + d;
            *(float2*)(ex + dst) = make_float2(c[mt][nt][0], c[mt][nt][1]);
            *(float2*)(ex + dst + 8 * kHD) = make_float2(c[mt][nt][2], c[mt][nt][3]);
            *(float2*)(rd + dst) = make_float2(rtf(c[mt][nt][0]), rtf(c[mt][nt][1]));
            *(float2*)(rd + dst + 8 * kHD) = make_float2(rtf(c[mt][nt][2]), rtf(c[mt][nt][3]));
          }
        }
      }
    });
}

// ---------------------------------------------------------------------------
// O-projection: out[M,N] = Ctx @ Wo^T (plain epilogue).
// ---------------------------------------------------------------------------
__global__ __launch_bounds__(256) void gemm_out(
    const float* __restrict__ A, const float* __restrict__ Bw,
    float* __restrict__ C, int N, int K) {
  extern __shared__ float smem[];
  const int n0 = blockIdx.x * 128;
  gemm_body(A, Bw + (long)n0 * K, K, smem,
    [&](const GemmCtx& g, float c[2][8][4]) {
#pragma unroll
      for (int mt = 0; mt < 2; mt++) {
        int mrow = g.m0 + g.wm0 + mt * 16 + g.lr8;
#pragma unroll
        for (int nt = 0; nt < 8; nt++) {
          int col = n0 + g.wn0 + nt * 8 + g.lq * 2;
          *(float2*)(C + (long)mrow * N + col) = make_float2(c[mt][nt][0], c[mt][nt][1]);
          *(float2*)(C + (long)(mrow + 8) * N + col) = make_float2(c[mt][nt][2], c[mt][nt][3]);
        }
      }
    });
}

// ---------------------------------------------------------------------------
// Flash attention, TF32 mma.sync, cp.async-pipelined K/V tiles.
// Q in [b,h,s,d] (pre-scaled/rounded); K/V in [b,g,s,d] (rounded).
// ---------------------------------------------------------------------------
__global__ __launch_bounds__(128) void attn_tf32(
    const float* __restrict__ Q, const float* __restrict__ Kc,
    const float* __restrict__ Vc, float* __restrict__ Ctx) {
  constexpr int LD = 68, LDV = 72;
  extern __shared__ float sm[];
  float* Qs = sm;                   // [128][LD]
  float* Ks = Qs + 128 * LD;        // [64][LD]
  float* Vs = Ks + 64 * LD;         // [64][LDV]
  float* Ps = Vs + 64 * LDV;        // [128][LD]

  const int qt = gridDim.x - 1 - blockIdx.x;   // heavy blocks first
  const int hb = blockIdx.y;
  const int b = hb >> 5, h = hb & 31, g = h >> 2;
  const int t = threadIdx.x, lane = t & 31, w = t >> 5;
  const int wq0 = w * 32;
  const int lq = lane & 3, lr8 = lane >> 2;
  const int q0 = qt * 128;

  const float* Qbase = Q  + ((long)(b * kNH + h) * kS + q0) * kHD;
  const float* Kbase = Kc + (long)(b * kNKV + g) * kS * kHD;
  const float* Vbase = Vc + (long)(b * kNKV + g) * kS * kHD;

  const uint32_t sK = (uint32_t)__cvta_generic_to_shared(Ks);
  const uint32_t sV = (uint32_t)__cvta_generic_to_shared(Vs);

  auto issue_K = [&](int k0) {
#pragma unroll
    for (int i = 0; i < 8; i++) {
      int chunk = t + i * 128;
      int r = chunk >> 4, cc = chunk & 15;
      cp_async16(sK + (uint32_t)(r * LD + cc * 4) * 4u, Kbase + (long)(k0 + r) * kHD + cc * 4);
    }
    asm volatile("cp.async.commit_group;" ::: "memory");
  };
  auto issue_V = [&](int k0) {
#pragma unroll
    for (int i = 0; i < 8; i++) {
      int chunk = t + i * 128;
      int r = chunk >> 4, cc = chunk & 15;
      cp_async16(sV + (uint32_t)(r * LDV + cc * 4) * 4u, Vbase + (long)(k0 + r) * kHD + cc * 4);
    }
    asm volatile("cp.async.commit_group;" ::: "memory");
  };

  issue_K(0);
  issue_V(0);

  {  // Q tile: contiguous rows
    const float* qp = Qbase + (long)t * kHD;
    float* dst = Qs + t * LD;
#pragma unroll
    for (int i = 0; i < 16; i++) *(float4*)(dst + i * 4) = *(const float4*)(qp + i * 4);
  }

  float out[2][8][4];
#pragma unroll
  for (int mt = 0; mt < 2; mt++)
#pragma unroll
    for (int nt = 0; nt < 8; nt++)
#pragma unroll
      for (int r = 0; r < 4; r++) out[mt][nt][r] = 0.f;
  float mrow[2][2] = {{-1e30f, -1e30f}, {-1e30f, -1e30f}};
  float lrow[2][2] = {{0.f, 0.f}, {0.f, 0.f}};

  const int nkt = 2 * qt + 2;
  for (int kt = 0; kt < nkt; kt++) {
    const int k0 = kt * 64;

    asm volatile("cp.async.wait_group 1;" ::: "memory");
    __syncthreads();

    // S = Q K^T
    float sc[2][8][4];
#pragma unroll
    for (int mt = 0; mt < 2; mt++)
#pragma unroll
      for (int nt = 0; nt < 8; nt++)
#pragma unroll
        for (int r = 0; r < 4; r++) sc[mt][nt][r] = 0.f;

#pragma unroll
    for (int ks = 0; ks < 8; ks++) {
      const int kb = ks * 8;
      uint32_t af[2][4], bf[8][2];
#pragma unroll
      for (int mt = 0; mt < 2; mt++) {
        const float* ap = Qs + (wq0 + mt * 16 + lr8) * LD + kb + lq;
        af[mt][0] = __float_as_uint(ap[0]);
        af[mt][1] = __float_as_uint(ap[8 * LD]);
        af[mt][2] = __float_as_uint(ap[4]);
        af[mt][3] = __float_as_uint(ap[8 * LD + 4]);
      }
#pragma unroll
      for (int nt = 0; nt < 8; nt++) {
        const float* bp = Ks + (nt * 8 + lr8) * LD + kb + lq;
        bf[nt][0] = __float_as_uint(bp[0]);
        bf[nt][1] = __float_as_uint(bp[4]);
      }
#pragma unroll
      for (int mt = 0; mt < 2; mt++)
#pragma unroll
        for (int nt = 0; nt < 8; nt++) mma_tf32(sc[mt][nt], af[mt], bf[nt]);
    }

    asm volatile("cp.async.wait_group 0;" ::: "memory");
    __syncthreads();
    if (kt + 1 < nkt) issue_K(k0 + 64);

    if (k0 + 63 > q0 + wq0) {
#pragma unroll
      for (int mt = 0; mt < 2; mt++) {
        int r0 = q0 + wq0 + mt * 16 + lr8;
        int r1 = r0 + 8;
#pragma unroll
        for (int nt = 0; nt < 8; nt++) {
          int col = k0 + nt * 8 + 2 * lq;
          if (col > r0)     sc[mt][nt][0] = -1e30f;
          if (col + 1 > r0) sc[mt][nt][1] = -1e30f;
          if (col > r1)     sc[mt][nt][2] = -1e30f;
          if (col + 1 > r1) sc[mt][nt][3] = -1e30f;
        }
      }
    }

#pragma unroll
    for (int mt = 0; mt < 2; mt++) {
      float mx0 = -1e30f, mx1 = -1e30f;
#pragma unroll
      for (int nt = 0; nt < 8; nt++) {
        mx0 = fmaxf(mx0, fmaxf(sc[mt][nt][0], sc[mt][nt][1]));
        mx1 = fmaxf(mx1, fmaxf(sc[mt][nt][2], sc[mt][nt][3]));
      }
      mx0 = fmaxf(mx0, __shfl_xor_sync(0xffffffffu, mx0, 1));
      mx0 = fmaxf(mx0, __shfl_xor_sync(0xffffffffu, mx0, 2));
      mx1 = fmaxf(mx1, __shfl_xor_sync(0xffffffffu, mx1, 1));
      mx1 = fmaxf(mx1, __shfl_xor_sync(0xffffffffu, mx1, 2));

      float mn0 = fmaxf(mrow[mt][0], mx0);
      float mn1 = fmaxf(mrow[mt][1], mx1);
      float e0 = fexp2(mrow[mt][0] - mn0);
      float e1 = fexp2(mrow[mt][1] - mn1);
      mrow[mt][0] = mn0; mrow[mt][1] = mn1;

      float s0 = 0.f, s1 = 0.f;
      float* pr0 = Ps + (wq0 + mt * 16 + lr8) * LD + 2 * lq;
      float* pr1 = pr0 + 8 * LD;
#pragma unroll
      for (int nt = 0; nt < 8; nt++) {
        float p0 = rtf(fexp2(sc[mt][nt][0] - mn0));
        float p1 = rtf(fexp2(sc[mt][nt][1] - mn0));
        float p2 = rtf(fexp2(sc[mt][nt][2] - mn1));
        float p3 = rtf(fexp2(sc[mt][nt][3] - mn1));
        s0 += p0 + p1;
        s1 += p2 + p3;
        *(float2*)(pr0 + nt * 8) = make_float2(p0, p1);
        *(float2*)(pr1 + nt * 8) = make_float2(p2, p3);
      }
      s0 += __shfl_xor_sync(0xffffffffu, s0, 1);
      s0 += __shfl_xor_sync(0xffffffffu, s0, 2);
      s1 += __shfl_xor_sync(0xffffffffu, s1, 1);
      s1 += __shfl_xor_sync(0xffffffffu, s1, 2);
      lrow[mt][0] = lrow[mt][0] * e0 + s0;
      lrow[mt][1] = lrow[mt][1] * e1 + s1;
#pragma unroll
      for (int nt = 0; nt < 8; nt++) {
        out[mt][nt][0] *= e0; out[mt][nt][1] *= e0;
        out[mt][nt][2] *= e1; out[mt][nt][3] *= e1;
      }
    }
    __syncwarp();

    // out += P V
#pragma unroll
    for (int ks = 0; ks < 8; ks++) {
      const int kb = ks * 8;
      uint32_t af[2][4], bf[8][2];
#pragma unroll
      for (int mt = 0; mt < 2; mt++) {
        const float* ap = Ps + (wq0 + mt * 16 + lr8) * LD + kb + lq;
        af[mt][0] = __float_as_uint(ap[0]);
        af[mt][1] = __float_as_uint(ap[8 * LD]);
        af[mt][2] = __float_as_uint(ap[4]);
        af[mt][3] = __float_as_uint(ap[8 * LD + 4]);
      }
#pragma unroll
      for (int nt = 0; nt < 8; nt++) {
        const float* vp = Vs + (kb + lq) * LDV + nt * 8 + lr8;
        bf[nt][0] = __float_as_uint(vp[0]);
        bf[nt][1] = __float_as_uint(vp[4 * LDV]);
      }
#pragma unroll
      for (int mt = 0; mt < 2; mt++)
#pragma unroll
        for (int nt = 0; nt < 8; nt++) mma_tf32(out[mt][nt], af[mt], bf[nt]);
    }
    __syncthreads();
    if (kt + 1 < nkt) issue_V(k0 + 64);
  }

  // Epilogue: normalize and store ctx ([b*s, 2048] row-major for O-proj)
  float* Cb = Ctx + (long)(b * kS + q0) * kDout + h * kHD;
#pragma unroll
  for (int mt = 0; mt < 2; mt++) {
    int r0 = wq0 + mt * 16 + lr8;
    float inv0 = 1.f / lrow[mt][0];
    float inv1 = 1.f / lrow[mt][1];
#pragma unroll
    for (int nt = 0; nt < 8; nt++) {
      int col = nt * 8 + 2 * lq;
      *(float2*)(Cb + (long)r0 * kDout + col) =
          make_float2(out[mt][nt][0] * inv0, out[mt][nt][1] * inv0);
      *(float2*)(Cb + (long)(r0 + 8) * kDout + col) =
          make_float2(out[mt][nt][2] * inv1, out[mt][nt][3] * inv1);
    }
  }
}

// ---------------------------------------------------------------------------
extern "C" void kernel_launch(void* const* d_in, const int* in_sizes, int n_in,
                              void* d_out, int out_size) {
  const float* x  = (const float*)d_in[0];
  const float* Wq = (const float*)d_in[1];
  const float* Wk = (const float*)d_in[2];
  const float* Wv = (const float*)d_in[3];
  const float* Wo = (const float*)d_in[4];

  float* out    = (float*)d_out;                    // [2,2048,2048]
  float* keys   = out + kM * kDout;                 // [2,8,2048,64]
  float* values = keys + kB * kNKV * kS * kHD;      // [2,8,2048,64]

  float *qb, *kr, *vr, *cb;
  cudaGetSymbolAddress((void**)&qb, g_Q);
  cudaGetSymbolAddress((void**)&kr, g_Kr);
  cudaGetSymbolAddress((void**)&vr, g_Vr);
  cudaGetSymbolAddress((void**)&cb, g_Ctx);

  constexpr int kGemmSmem = 4 * 128 * 36 * (int)sizeof(float);   // 73728 B
  constexpr int kAttnSmem =
      (128 * 68 + 64 * 68 + 64 * 72 + 128 * 68) * (int)sizeof(float);  // 105472 B
  static bool attr_set = false;
  if (!attr_set) {
    cudaFuncSetAttribute(proj_qkv, cudaFuncAttributeMaxDynamicSharedMemorySize, kGemmSmem);
    cudaFuncSetAttribute(gemm_out, cudaFuncAttributeMaxDynamicSharedMemorySize, kGemmSmem);
    cudaFuncSetAttribute(attn_tf32, cudaFuncAttributeMaxDynamicSharedMemorySize, kAttnSmem);
    attr_set = true;
  }

  // Fused Q/K/V projections (one launch, all epilogue layouts final)
  proj_qkv<<<dim3(24, kM / 128), 256, kGemmSmem>>>(
      x, Wq, Wk, Wv, qb, keys, values, kr, vr);
  // Attention (TF32 tensor cores, cp.async pipelined)
  attn_tf32<<<dim3(kS / 128, kB * kNH), dim3(128), kAttnSmem>>>(qb, kr, vr, cb);
  // Output projection
  gemm_out<<<dim3(kDout / 128, kM / 128), 256, kGemmSmem>>>(cb, Wo, out, kDout, kDin);
}

// round 9
// speedup vs baseline: 4.0037x; 1.0182x over previous
#include <cuda_runtime.h>
#include <cstdint>

// Problem constants
namespace {
constexpr int kB   = 2;
constexpr int kS   = 2048;
constexpr int kDin = 2048;
constexpr int kNH  = 32;
constexpr int kNKV = 8;
constexpr int kHD  = 64;
constexpr int kDout = 2048;           // kNH * kHD
constexpr int kM   = kB * kS;         // 4096 rows
constexpr int kKV  = kNKV * kHD;      // 512
// combined scale: (1/sqrt(64)) * log2(e) so softmax uses raw EX2
constexpr float kQScale = 0.18033688f;
}

// Scratch (static device arrays; cudaMalloc is forbidden)
__device__ float g_Q[kM * kDout];       // 32 MB (pre-scaled, tf32-rounded, [b,h,s,d])
__device__ float g_Kr[kM * kKV];        // 8 MB (tf32-rounded, [b,g,s,d])
__device__ float g_Vr[kM * kKV];        // 8 MB (tf32-rounded, [b,g,s,d])
__device__ float g_Ctx[kM * kDout];     // 32 MB (tf32-rounded)
__device__ float g_xr[kM * kDin];       // 32 MB (tf32-rounded inputs/weights)
__device__ float g_Wqr[kDout * kDin];   // 16 MB
__device__ float g_Wkr[kKV * kDin];     // 4 MB
__device__ float g_Wvr[kKV * kDin];     // 4 MB
__device__ float g_Wor[kDin * kDout];   // 16 MB

__device__ __forceinline__ uint32_t f2tf32(float f) {
  uint32_t u;
  asm("cvt.rna.tf32.f32 %0, %1;" : "=r"(u) : "f"(f));
  return u;
}
__device__ __forceinline__ float rtf(float f) { return __uint_as_float(f2tf32(f)); }

__device__ __forceinline__ float fexp2(float x) {
  float y;
  asm("ex2.approx.ftz.f32 %0, %1;" : "=f"(y) : "f"(x));
  return y;
}

__device__ __forceinline__ void cp_async16(uint32_t smem_addr, const void* gptr) {
  asm volatile("cp.async.cg.shared.global [%0], [%1], 16;" :: "r"(smem_addr), "l"(gptr));
}

__device__ __forceinline__ void mma_tf32(float* c, const uint32_t* a, const uint32_t* b) {
  asm volatile(
      "mma.sync.aligned.m16n8k8.row.col.f32.tf32.tf32.f32 "
      "{%0,%1,%2,%3}, {%4,%5,%6,%7}, {%8,%9}, {%0,%1,%2,%3};"
      : "+f"(c[0]), "+f"(c[1]), "+f"(c[2]), "+f"(c[3])
      : "r"(a[0]), "r"(a[1]), "r"(a[2]), "r"(a[3]), "r"(b[0]), "r"(b[1]));
}

// ---------------------------------------------------------------------------
// Pre-round all GEMM operands to TF32 in one streaming launch.
// Segments: x, Wq, Wk, Wv, Wo (float4 granularity).
// ---------------------------------------------------------------------------
__global__ __launch_bounds__(256) void round5(
    const float4* __restrict__ x,  float4* __restrict__ xr,  int n0,
    const float4* __restrict__ wq, float4* __restrict__ wqr, int n1,
    const float4* __restrict__ wk, float4* __restrict__ wkr, int n2,
    const float4* __restrict__ wv, float4* __restrict__ wvr, int n3,
    const float4* __restrict__ wo, float4* __restrict__ wor, int n4) {
  int i = blockIdx.x * 256 + threadIdx.x;
  const float4* s; float4* d;
  if (i < n0) { s = x + i;  d = xr + i; }
  else if ((i -= n0) < n1) { s = wq + i; d = wqr + i; }
  else if ((i -= n1) < n2) { s = wk + i; d = wkr + i; }
  else if ((i -= n2) < n3) { s = wv + i; d = wvr + i; }
  else if ((i -= n3) < n4) { s = wo + i; d = wor + i; }
  else return;
  float4 v = *s;
  *d = make_float4(rtf(v.x), rtf(v.y), rtf(v.z), rtf(v.w));
}

// ---------------------------------------------------------------------------
// TF32 GEMM mainloop (128x128x32, double buffer). Operands pre-rounded ->
// fragment loads are raw uint LDS, no cvt in the mainloop.
// ---------------------------------------------------------------------------
struct GemmCtx {
  int m0, wm0, wn0, lq, lr8;
};

template <typename Epi>
__device__ __forceinline__ void gemm_body(
    const float* __restrict__ A, const float* __restrict__ Bw,
    int K, float* smem, Epi&& epilogue) {
  constexpr int BM = 128, BN = 128, BK = 32, LD = 36;
  float* As = smem;
  float* Bs = smem + 2 * BM * LD;

  const int m0 = blockIdx.y * BM;
  const int t = threadIdx.x;
  const int lane = t & 31, w = t >> 5;
  const int wm0 = (w & 3) * 32;
  const int wn0 = (w >> 2) * 64;
  const int lq = lane & 3;
  const int lr8 = lane >> 2;
  const int grow = t >> 3;
  const int gk4  = (t & 7) * 4;

  const float* Agp = A  + (m0 + grow) * (long)K + gk4;
  const float* Bgp = Bw + grow * (long)K + gk4;   // n0 pre-applied by caller

  uint32_t sA = (uint32_t)__cvta_generic_to_shared(As);
  uint32_t sB = (uint32_t)__cvta_generic_to_shared(Bs);

  auto load_stage = [&](int buf, int k0) {
    uint32_t abase = sA + (uint32_t)(buf * BM * LD) * 4u;
    uint32_t bbase = sB + (uint32_t)(buf * BN * LD) * 4u;
#pragma unroll
    for (int s = 0; s < 4; s++) {
      int row = grow + s * 32;
      cp_async16(abase + (uint32_t)(row * LD + gk4) * 4u, Agp + (long)s * 32 * K + k0);
      cp_async16(bbase + (uint32_t)(row * LD + gk4) * 4u, Bgp + (long)s * 32 * K + k0);
    }
    asm volatile("cp.async.commit_group;" ::: "memory");
  };

  float c[2][8][4];
#pragma unroll
  for (int i = 0; i < 2; i++)
#pragma unroll
    for (int j = 0; j < 8; j++)
#pragma unroll
      for (int r = 0; r < 4; r++) c[i][j][r] = 0.f;

  const int NIT = K / BK;
  load_stage(0, 0);

  for (int it = 0; it < NIT; it++) {
    if (it + 1 < NIT) {
      load_stage((it + 1) & 1, (it + 1) * BK);
      asm volatile("cp.async.wait_group 1;" ::: "memory");
    } else {
      asm volatile("cp.async.wait_group 0;" ::: "memory");
    }
    __syncthreads();

    const float* Ab = As + (it & 1) * BM * LD;
    const float* Bb = Bs + (it & 1) * BN * LD;

#pragma unroll
    for (int ks = 0; ks < 4; ks++) {
      const int kb = ks * 8;
      uint32_t af[2][4], bf[8][2];
#pragma unroll
      for (int mt = 0; mt < 2; mt++) {
        const uint32_t* ap = (const uint32_t*)(Ab + (wm0 + mt * 16 + lr8) * LD + kb + lq);
        af[mt][0] = ap[0];
        af[mt][1] = ap[8 * LD];
        af[mt][2] = ap[4];
        af[mt][3] = ap[8 * LD + 4];
      }
#pragma unroll
      for (int nt = 0; nt < 8; nt++) {
        const uint32_t* bp = (const uint32_t*)(Bb + (wn0 + nt * 8 + lr8) * LD + kb + lq);
        bf[nt][0] = bp[0];
        bf[nt][1] = bp[4];
      }
#pragma unroll
      for (int mt = 0; mt < 2; mt++)
#pragma unroll
        for (int nt = 0; nt < 8; nt++) mma_tf32(c[mt][nt], af[mt], bf[nt]);
    }
    __syncthreads();
  }

  GemmCtx ctx{m0, wm0, wn0, lq, lr8};
  epilogue(ctx, c);
}

// ---------------------------------------------------------------------------
// Fused Q/K/V projection. grid = (24, 32):
//   blockIdx.x  0..15 -> Q n-tile   epilogue: scale+round -> g_Q [b,h,s,d]
//   blockIdx.x 16..19 -> K n-tile   epilogue: keys exact + Kr rounded [b,g,s,d]
//   blockIdx.x 20..23 -> V n-tile   epilogue: values exact + Vr rounded
// ---------------------------------------------------------------------------
__global__ __launch_bounds__(256) void proj_qkv(
    const float* __restrict__ x, const float* __restrict__ Wq,
    const float* __restrict__ Wk, const float* __restrict__ Wv,
    float* __restrict__ Qo, float* __restrict__ keys, float* __restrict__ values,
    float* __restrict__ Kr, float* __restrict__ Vr) {
  extern __shared__ float smem[];
  const int bx = blockIdx.x;
  const float* Bw;
  int n0, which;
  if (bx < 16)      { Bw = Wq; n0 = bx * 128;        which = 0; }
  else if (bx < 20) { Bw = Wk; n0 = (bx - 16) * 128; which = 1; }
  else              { Bw = Wv; n0 = (bx - 20) * 128; which = 2; }

  gemm_body(x, Bw + (long)n0 * kDin, kDin, smem,
    [&](const GemmCtx& g, float c[2][8][4]) {
      float* ex = (which == 1) ? keys : values;
      float* rd = (which == 1) ? Kr : Vr;
#pragma unroll
      for (int mt = 0; mt < 2; mt++) {
        int mrow = g.m0 + g.wm0 + mt * 16 + g.lr8;
        int b = mrow >> 11, s = mrow & 2047;
#pragma unroll
        for (int nt = 0; nt < 8; nt++) {
          int coln = n0 + g.wn0 + nt * 8 + g.lq * 2;
          int head = coln >> 6, d = coln & 63;
          if (which == 0) {
            long dst = ((long)(b * kNH + head) * kS + s) * kHD + d;
            *(float2*)(Qo + dst) =
                make_float2(rtf(c[mt][nt][0] * kQScale), rtf(c[mt][nt][1] * kQScale));
            *(float2*)(Qo + dst + 8 * kHD) =
                make_float2(rtf(c[mt][nt][2] * kQScale), rtf(c[mt][nt][3] * kQScale));
          } else {
            long dst = ((long)(b * kNKV + head) * kS + s) * kHD + d;
            *(float2*)(ex + dst) = make_float2(c[mt][nt][0], c[mt][nt][1]);
            *(float2*)(ex + dst + 8 * kHD) = make_float2(c[mt][nt][2], c[mt][nt][3]);
            *(float2*)(rd + dst) = make_float2(rtf(c[mt][nt][0]), rtf(c[mt][nt][1]));
            *(float2*)(rd + dst + 8 * kHD) = make_float2(rtf(c[mt][nt][2]), rtf(c[mt][nt][3]));
          }
        }
      }
    });
}

// ---------------------------------------------------------------------------
// O-projection: out[M,N] = Ctx @ Wo^T (plain epilogue).
// ---------------------------------------------------------------------------
__global__ __launch_bounds__(256) void gemm_out(
    const float* __restrict__ A, const float* __restrict__ Bw,
    float* __restrict__ C, int N, int K) {
  extern __shared__ float smem[];
  const int n0 = blockIdx.x * 128;
  gemm_body(A, Bw + (long)n0 * K, K, smem,
    [&](const GemmCtx& g, float c[2][8][4]) {
#pragma unroll
      for (int mt = 0; mt < 2; mt++) {
        int mrow = g.m0 + g.wm0 + mt * 16 + g.lr8;
#pragma unroll
        for (int nt = 0; nt < 8; nt++) {
          int col = n0 + g.wn0 + nt * 8 + g.lq * 2;
          *(float2*)(C + (long)mrow * N + col) = make_float2(c[mt][nt][0], c[mt][nt][1]);
          *(float2*)(C + (long)(mrow + 8) * N + col) = make_float2(c[mt][nt][2], c[mt][nt][3]);
        }
      }
    });
}

// ---------------------------------------------------------------------------
// Flash attention, TF32 mma.sync, cp.async-pipelined K/V tiles.
// Q in [b,h,s,d] (pre-scaled/rounded); K/V in [b,g,s,d] (rounded).
// Ctx written tf32-rounded for the O-projection.
// ---------------------------------------------------------------------------
__global__ __launch_bounds__(128) void attn_tf32(
    const float* __restrict__ Q, const float* __restrict__ Kc,
    const float* __restrict__ Vc, float* __restrict__ Ctx) {
  constexpr int LD = 68, LDV = 72;
  extern __shared__ float sm[];
  float* Qs = sm;                   // [128][LD]
  float* Ks = Qs + 128 * LD;        // [64][LD]
  float* Vs = Ks + 64 * LD;         // [64][LDV]
  float* Ps = Vs + 64 * LDV;        // [128][LD]

  const int qt = gridDim.x - 1 - blockIdx.x;   // heavy blocks first
  const int hb = blockIdx.y;
  const int b = hb >> 5, h = hb & 31, g = h >> 2;
  const int t = threadIdx.x, lane = t & 31, w = t >> 5;
  const int wq0 = w * 32;
  const int lq = lane & 3, lr8 = lane >> 2;
  const int q0 = qt * 128;

  const float* Qbase = Q  + ((long)(b * kNH + h) * kS + q0) * kHD;
  const float* Kbase = Kc + (long)(b * kNKV + g) * kS * kHD;
  const float* Vbase = Vc + (long)(b * kNKV + g) * kS * kHD;

  const uint32_t sK = (uint32_t)__cvta_generic_to_shared(Ks);
  const uint32_t sV = (uint32_t)__cvta_generic_to_shared(Vs);

  auto issue_K = [&](int k0) {
#pragma unroll
    for (int i = 0; i < 8; i++) {
      int chunk = t + i * 128;
      int r = chunk >> 4, cc = chunk & 15;
      cp_async16(sK + (uint32_t)(r * LD + cc * 4) * 4u, Kbase + (long)(k0 + r) * kHD + cc * 4);
    }
    asm volatile("cp.async.commit_group;" ::: "memory");
  };
  auto issue_V = [&](int k0) {
#pragma unroll
    for (int i = 0; i < 8; i++) {
      int chunk = t + i * 128;
      int r = chunk >> 4, cc = chunk & 15;
      cp_async16(sV + (uint32_t)(r * LDV + cc * 4) * 4u, Vbase + (long)(k0 + r) * kHD + cc * 4);
    }
    asm volatile("cp.async.commit_group;" ::: "memory");
  };

  issue_K(0);
  issue_V(0);

  {  // Q tile: contiguous rows
    const float* qp = Qbase + (long)t * kHD;
    float* dst = Qs + t * LD;
#pragma unroll
    for (int i = 0; i < 16; i++) *(float4*)(dst + i * 4) = *(const float4*)(qp + i * 4);
  }

  float out[2][8][4];
#pragma unroll
  for (int mt = 0; mt < 2; mt++)
#pragma unroll
    for (int nt = 0; nt < 8; nt++)
#pragma unroll
      for (int r = 0; r < 4; r++) out[mt][nt][r] = 0.f;
  float mrow[2][2] = {{-1e30f, -1e30f}, {-1e30f, -1e30f}};
  float lrow[2][2] = {{0.f, 0.f}, {0.f, 0.f}};

  const int nkt = 2 * qt + 2;
  for (int kt = 0; kt < nkt; kt++) {
    const int k0 = kt * 64;

    asm volatile("cp.async.wait_group 1;" ::: "memory");
    __syncthreads();

    // S = Q K^T
    float sc[2][8][4];
#pragma unroll
    for (int mt = 0; mt < 2; mt++)
#pragma unroll
      for (int nt = 0; nt < 8; nt++)
#pragma unroll
        for (int r = 0; r < 4; r++) sc[mt][nt][r] = 0.f;

#pragma unroll
    for (int ks = 0; ks < 8; ks++) {
      const int kb = ks * 8;
      uint32_t af[2][4], bf[8][2];
#pragma unroll
      for (int mt = 0; mt < 2; mt++) {
        const uint32_t* ap = (const uint32_t*)(Qs + (wq0 + mt * 16 + lr8) * LD + kb + lq);
        af[mt][0] = ap[0];
        af[mt][1] = ap[8 * LD];
        af[mt][2] = ap[4];
        af[mt][3] = ap[8 * LD + 4];
      }
#pragma unroll
      for (int nt = 0; nt < 8; nt++) {
        const uint32_t* bp = (const uint32_t*)(Ks + (nt * 8 + lr8) * LD + kb + lq);
        bf[nt][0] = bp[0];
        bf[nt][1] = bp[4];
      }
#pragma unroll
      for (int mt = 0; mt < 2; mt++)
#pragma unroll
        for (int nt = 0; nt < 8; nt++) mma_tf32(sc[mt][nt], af[mt], bf[nt]);
    }

    asm volatile("cp.async.wait_group 0;" ::: "memory");
    __syncthreads();
    if (kt + 1 < nkt) issue_K(k0 + 64);

    if (k0 + 63 > q0 + wq0) {
#pragma unroll
      for (int mt = 0; mt < 2; mt++) {
        int r0 = q0 + wq0 + mt * 16 + lr8;
        int r1 = r0 + 8;
#pragma unroll
        for (int nt = 0; nt < 8; nt++) {
          int col = k0 + nt * 8 + 2 * lq;
          if (col > r0)     sc[mt][nt][0] = -1e30f;
          if (col + 1 > r0) sc[mt][nt][1] = -1e30f;
          if (col > r1)     sc[mt][nt][2] = -1e30f;
          if (col + 1 > r1) sc[mt][nt][3] = -1e30f;
        }
      }
    }

#pragma unroll
    for (int mt = 0; mt < 2; mt++) {
      float mx0 = -1e30f, mx1 = -1e30f;
#pragma unroll
      for (int nt = 0; nt < 8; nt++) {
        mx0 = fmaxf(mx0, fmaxf(sc[mt][nt][0], sc[mt][nt][1]));
        mx1 = fmaxf(mx1, fmaxf(sc[mt][nt][2], sc[mt][nt][3]));
      }
      mx0 = fmaxf(mx0, __shfl_xor_sync(0xffffffffu, mx0, 1));
      mx0 = fmaxf(mx0, __shfl_xor_sync(0xffffffffu, mx0, 2));
      mx1 = fmaxf(mx1, __shfl_xor_sync(0xffffffffu, mx1, 1));
      mx1 = fmaxf(mx1, __shfl_xor_sync(0xffffffffu, mx1, 2));

      float mn0 = fmaxf(mrow[mt][0], mx0);
      float mn1 = fmaxf(mrow[mt][1], mx1);
      float e0 = fexp2(mrow[mt][0] - mn0);
      float e1 = fexp2(mrow[mt][1] - mn1);
      mrow[mt][0] = mn0; mrow[mt][1] = mn1;

      float s0 = 0.f, s1 = 0.f;
      float* pr0 = Ps + (wq0 + mt * 16 + lr8) * LD + 2 * lq;
      float* pr1 = pr0 + 8 * LD;
#pragma unroll
      for (int nt = 0; nt < 8; nt++) {
        float p0 = rtf(fexp2(sc[mt][nt][0] - mn0));
        float p1 = rtf(fexp2(sc[mt][nt][1] - mn0));
        float p2 = rtf(fexp2(sc[mt][nt][2] - mn1));
        float p3 = rtf(fexp2(sc[mt][nt][3] - mn1));
        s0 += p0 + p1;
        s1 += p2 + p3;
        *(float2*)(pr0 + nt * 8) = make_float2(p0, p1);
        *(float2*)(pr1 + nt * 8) = make_float2(p2, p3);
      }
      s0 += __shfl_xor_sync(0xffffffffu, s0, 1);
      s0 += __shfl_xor_sync(0xffffffffu, s0, 2);
      s1 += __shfl_xor_sync(0xffffffffu, s1, 1);
      s1 += __shfl_xor_sync(0xffffffffu, s1, 2);
      lrow[mt][0] = lrow[mt][0] * e0 + s0;
      lrow[mt][1] = lrow[mt][1] * e1 + s1;
#pragma unroll
      for (int nt = 0; nt < 8; nt++) {
        out[mt][nt][0] *= e0; out[mt][nt][1] *= e0;
        out[mt][nt][2] *= e1; out[mt][nt][3] *= e1;
      }
    }
    __syncwarp();

    // out += P V
#pragma unroll
    for (int ks = 0; ks < 8; ks++) {
      const int kb = ks * 8;
      uint32_t af[2][4], bf[8][2];
#pragma unroll
      for (int mt = 0; mt < 2; mt++) {
        const uint32_t* ap = (const uint32_t*)(Ps + (wq0 + mt * 16 + lr8) * LD + kb + lq);
        af[mt][0] = ap[0];
        af[mt][1] = ap[8 * LD];
        af[mt][2] = ap[4];
        af[mt][3] = ap[8 * LD + 4];
      }
#pragma unroll
      for (int nt = 0; nt < 8; nt++) {
        const uint32_t* vp = (const uint32_t*)(Vs + (kb + lq) * LDV + nt * 8 + lr8);
        bf[nt][0] = vp[0];
        bf[nt][1] = vp[4 * LDV];
      }
#pragma unroll
      for (int mt = 0; mt < 2; mt++)
#pragma unroll
        for (int nt = 0; nt < 8; nt++) mma_tf32(out[mt][nt], af[mt], bf[nt]);
    }
    __syncthreads();
    if (kt + 1 < nkt) issue_V(k0 + 64);
  }

  // Epilogue: normalize, round to tf32, store ctx ([b*s, 2048] for O-proj)
  float* Cb = Ctx + (long)(b * kS + q0) * kDout + h * kHD;
#pragma unroll
  for (int mt = 0; mt < 2; mt++) {
    int r0 = wq0 + mt * 16 + lr8;
    float inv0 = 1.f / lrow[mt][0];
    float inv1 = 1.f / lrow[mt][1];
#pragma unroll
    for (int nt = 0; nt < 8; nt++) {
      int col = nt * 8 + 2 * lq;
      *(float2*)(Cb + (long)r0 * kDout + col) =
          make_float2(rtf(out[mt][nt][0] * inv0), rtf(out[mt][nt][1] * inv0));
      *(float2*)(Cb + (long)(r0 + 8) * kDout + col) =
          make_float2(rtf(out[mt][nt][2] * inv1), rtf(out[mt][nt][3] * inv1));
    }
  }
}

// ---------------------------------------------------------------------------
extern "C" void kernel_launch(void* const* d_in, const int* in_sizes, int n_in,
                              void* d_out, int out_size) {
  const float* x  = (const float*)d_in[0];
  const float* Wq = (const float*)d_in[1];
  const float* Wk = (const float*)d_in[2];
  const float* Wv = (const float*)d_in[3];
  const float* Wo = (const float*)d_in[4];

  float* out    = (float*)d_out;                    // [2,2048,2048]
  float* keys   = out + kM * kDout;                 // [2,8,2048,64]
  float* values = keys + kB * kNKV * kS * kHD;      // [2,8,2048,64]

  float *qb, *kr, *vr, *cb, *xr, *wqr, *wkr, *wvr, *wor;
  cudaGetSymbolAddress((void**)&qb, g_Q);
  cudaGetSymbolAddress((void**)&kr, g_Kr);
  cudaGetSymbolAddress((void**)&vr, g_Vr);
  cudaGetSymbolAddress((void**)&cb, g_Ctx);
  cudaGetSymbolAddress((void**)&xr, g_xr);
  cudaGetSymbolAddress((void**)&wqr, g_Wqr);
  cudaGetSymbolAddress((void**)&wkr, g_Wkr);
  cudaGetSymbolAddress((void**)&wvr, g_Wvr);
  cudaGetSymbolAddress((void**)&wor, g_Wor);

  constexpr int kGemmSmem = 4 * 128 * 36 * (int)sizeof(float);   // 73728 B
  constexpr int kAttnSmem =
      (128 * 68 + 64 * 68 + 64 * 72 + 128 * 68) * (int)sizeof(float);  // 105472 B
  static bool attr_set = false;
  if (!attr_set) {
    cudaFuncSetAttribute(proj_qkv, cudaFuncAttributeMaxDynamicSharedMemorySize, kGemmSmem);
    cudaFuncSetAttribute(gemm_out, cudaFuncAttributeMaxDynamicSharedMemorySize, kGemmSmem);
    cudaFuncSetAttribute(attn_tf32, cudaFuncAttributeMaxDynamicSharedMemorySize, kAttnSmem);
    attr_set = true;
  }

  // 0. Pre-round all GEMM operands to TF32 (numerics identical to in-loop cvt)
  constexpr int n0 = kM * kDin / 4;      // x
  constexpr int n1 = kDout * kDin / 4;   // Wq
  constexpr int n2 = kKV * kDin / 4;     // Wk
  constexpr int n3 = kKV * kDin / 4;     // Wv
  constexpr int n4 = kDin * kDout / 4;   // Wo
  constexpr int ntot = n0 + n1 + n2 + n3 + n4;
  round5<<<(ntot + 255) / 256, 256>>>(
      (const float4*)x,  (float4*)xr,  n0,
      (const float4*)Wq, (float4*)wqr, n1,
      (const float4*)Wk, (float4*)wkr, n2,
      (const float4*)Wv, (float4*)wvr, n3,
      (const float4*)Wo, (float4*)wor, n4);

  // 1. Fused Q/K/V projections
  proj_qkv<<<dim3(24, kM / 128), 256, kGemmSmem>>>(
      xr, wqr, wkr, wvr, qb, keys, values, kr, vr);
  // 2. Attention (TF32 tensor cores, cp.async pipelined)
  attn_tf32<<<dim3(kS / 128, kB * kNH), dim3(128), kAttnSmem>>>(qb, kr, vr, cb);
  // 3. Output projection
  gemm_out<<<dim3(kDout / 128, kM / 128), 256, kGemmSmem>>>(cb, wor, out, kDout, kDin);
}